// round 12
// baseline (speedup 1.0000x reference)
#include <cuda_runtime.h>
#include <cuda_bf16.h>
#include <math.h>
#include <stdint.h>

// ---------------- problem constants ----------------
#define NN     16384
#define BB     4096
#define EE     131072
#define MEMD   256
#define TDD    128
#define MSGD   172
#define GRUIN  812
#define G3     768

// padded K dims (multiples of 16 halves -> no k-guards in pipeline)
#define K_GI   816     // 812 real + 4 zero
#define K_ATT  320     // 172 msg + 4 zero + 128 te + 16 zero
#define ATT_TE0 176

// ---------------- device scratch ----------------
__device__ __nv_bfloat16 g_aggrbf[(size_t)NN * K_GI];
__device__ __nv_bfloat16 g_hbf   [(size_t)NN * MEMD];
__device__ __nv_bfloat16 g_membf [(size_t)NN * MEMD];
__device__ __nv_bfloat16 g_zbf   [(size_t)NN * MEMD];
__device__ __nv_bfloat16 g_qkvbf [(size_t)NN * 1024];   // [q | k | v | skip] bf16
__device__ __nv_bfloat16 g_wih_bf[768 * K_GI];
__device__ __nv_bfloat16 g_whh_bf[768 * 256];
__device__ __nv_bfloat16 g_wq_bf [256 * 256];
__device__ __nv_bfloat16 g_wk_bf [256 * 256];
__device__ __nv_bfloat16 g_wv_bf [256 * 256];
__device__ __nv_bfloat16 g_ws_bf [256 * 256];
__device__ __nv_bfloat16 g_we_bf [256 * K_ATT];
__device__ __nv_bfloat16 g_lph_bf[256 * 512];

__device__ float g_lu   [NN];
__device__ float g_gi   [(size_t)NN * G3];
__device__ float g_gh   [(size_t)NN * G3];
__device__ float g_denom[(size_t)NN * 2];
__device__ float g_agg  [(size_t)NN * MEMD];
__device__ float g_hid  [(size_t)2 * BB * 256];

// ---------------- tiles (R9/R11 champion parameters) ----------------
#define TBM 128
#define TBN 128
#define TBK 16          // k-halves per tile
#define KPADH 24        // padded row length in halves -> conflict-free
#define WPR 12          // words per SMEM row
#define STG 4
#define SMEM_BYTES (2 * STG * TBM * KPADH * 2)   // 49152

#define MMA_BF16(acc, af, bf)                                              \
    asm volatile(                                                          \
        "mma.sync.aligned.m16n8k16.row.col.f32.bf16.bf16.f32 "             \
        "{%0,%1,%2,%3}, {%4,%5,%6,%7}, {%8,%9}, {%0,%1,%2,%3};"            \
        : "+f"(acc[0]), "+f"(acc[1]), "+f"(acc[2]), "+f"(acc[3])           \
        : "r"(af[0]), "r"(af[1]), "r"(af[2]), "r"(af[3]),                  \
          "r"(bf[0]), "r"(bf[1]))

__device__ __forceinline__ void cp16(uint32_t dst, const void* src) {
    asm volatile("cp.async.cg.shared.global [%0], [%1], 16;"
                 :: "r"(dst), "l"(src));
}
#define CP_COMMIT asm volatile("cp.async.commit_group;")
#define CP_WAIT2  asm volatile("cp.async.wait_group 2;")

__device__ __forceinline__ unsigned pk(float a, float b) {
    unsigned x = (unsigned)__bfloat16_as_ushort(__float2bfloat16(a));
    unsigned y = (unsigned)__bfloat16_as_ushort(__float2bfloat16(b));
    return x | (y << 16);
}
__device__ __forceinline__ uint2 f4bf(float4 v) {
    return make_uint2(pk(v.x, v.y), pk(v.z, v.w));
}
__device__ __forceinline__ float2 bf2f(unsigned u) {
    __nv_bfloat162 h = *reinterpret_cast<__nv_bfloat162*>(&u);
    return __bfloat1622float2(h);
}

// ================= bf16 cp.async tensor GEMM =================
// MODE 0: plain bf16 A. MODE 2: link-pred pair gather. MODE 3: 4 stacked W.
// out_bf != 0 -> pack outputs to bf16 (C reinterpreted).
template<int MODE>
__global__ __launch_bounds__(256) void gemm5(
    const __nv_bfloat16* __restrict__ A, int strideA,
    const int* __restrict__ gidx,
    const __nv_bfloat16* __restrict__ W0c, const __nv_bfloat16* __restrict__ W1c,
    const __nv_bfloat16* __restrict__ W2c, const __nv_bfloat16* __restrict__ W3c,
    const float* __restrict__ b0c, const float* __restrict__ b1c,
    const float* __restrict__ b2c, const float* __restrict__ b3c,
    float* __restrict__ C, int Nout, int K, int do_relu, int out_bf)
{
    extern __shared__ unsigned dynsmem[];
    unsigned* As32 = dynsmem;                      // [STG][128][WPR]
    unsigned* Ws32 = dynsmem + STG * TBM * WPR;
    const uint32_t sb_a = (uint32_t)__cvta_generic_to_shared(dynsmem);
    const uint32_t sb_w = sb_a + STG * TBM * KPADH * 2;

    const int t    = threadIdx.x;
    const int warp = t >> 5;
    const int lane = t & 31;
    const int g    = lane >> 2;
    const int tig  = lane & 3;
    const int wm   = warp >> 2;
    const int wn   = warp & 3;
    const int row0 = blockIdx.y * TBM;
    const int col0 = blockIdx.x * TBN;

    const __nv_bfloat16* Wsel = W0c;
    const float* bsel = b0c;
    int colL = col0;
    if (MODE == 3) {
        int grp = col0 >> 8;
        Wsel = (grp == 0) ? W0c : (grp == 1) ? W1c : (grp == 2) ? W2c : W3c;
        bsel = (grp == 0) ? b0c : (grp == 1) ? b1c : (grp == 2) ? b2c : b3c;
        colL = col0 & 255;
    }

    float acc[4][4][4];
    #pragma unroll
    for (int i = 0; i < 4; i++)
        #pragma unroll
        for (int j = 0; j < 4; j++)
            #pragma unroll
            for (int c = 0; c < 4; c++) acc[i][j][c] = 0.f;

    const int r  = t >> 1;
    const int ch = t & 1;

    auto issue = [&](int s, int k0) {
        int kb = k0 + ch * 8;
        const __nv_bfloat16* srcA;
        if (MODE == 2) {
            int gr = row0 + r;
            int b = gr & (BB - 1), side = gr >> 12;
            if (kb < 256) srcA = A + (size_t)gidx[b] * 256 + kb;
            else          srcA = A + (size_t)gidx[BB + side * BB + b] * 256 + (kb - 256);
        } else {
            srcA = A + (size_t)(row0 + r) * strideA + kb;
        }
        uint32_t off = (uint32_t)(((s * TBM + r) * KPADH + ch * 8) * 2);
        cp16(sb_a + off, srcA);
        cp16(sb_w + off, Wsel + (size_t)(colL + r) * K + kb);
    };
    auto compute = [&](int buf) {
        unsigned af[4][4], bf[4][2];
        #pragma unroll
        for (int mt = 0; mt < 4; mt++) {
            int rb = (buf * TBM) + wm * 64 + mt * 16;
            af[mt][0] = As32[(rb + g    ) * WPR + tig];
            af[mt][1] = As32[(rb + g + 8) * WPR + tig];
            af[mt][2] = As32[(rb + g    ) * WPR + tig + 4];
            af[mt][3] = As32[(rb + g + 8) * WPR + tig + 4];
        }
        #pragma unroll
        for (int nt = 0; nt < 4; nt++) {
            int nb = (buf * TBN) + wn * 32 + nt * 8;
            bf[nt][0] = Ws32[(nb + g) * WPR + tig];
            bf[nt][1] = Ws32[(nb + g) * WPR + tig + 4];
        }
        #pragma unroll
        for (int mt = 0; mt < 4; mt++)
            #pragma unroll
            for (int nt = 0; nt < 4; nt++)
                MMA_BF16(acc[mt][nt], af[mt], bf[nt]);
    };

    const int ktiles = K / TBK;
    issue(0, 0);       CP_COMMIT;
    issue(1, TBK);     CP_COMMIT;
    issue(2, 2 * TBK); CP_COMMIT;
    int fetch = 3;
    for (int j = 0; j < ktiles; j++) {
        CP_WAIT2;
        __syncthreads();
        compute(j % STG);
        if (fetch < ktiles) { issue(fetch % STG, fetch * TBK); fetch++; }
        CP_COMMIT;
    }

    __nv_bfloat16* Cb = reinterpret_cast<__nv_bfloat16*>(C);
    #pragma unroll
    for (int mt = 0; mt < 4; mt++) {
        int gr = row0 + wm * 64 + mt * 16 + g;
        #pragma unroll
        for (int nt = 0; nt < 4; nt++) {
            int nl = colL + wn * 32 + nt * 8 + tig * 2;
            int gc = col0 + wn * 32 + nt * 8 + tig * 2;
            float bb0 = bsel ? bsel[nl]     : 0.f;
            float bb1 = bsel ? bsel[nl + 1] : 0.f;
            float v0 = acc[mt][nt][0] + bb0;
            float v1 = acc[mt][nt][1] + bb1;
            float v2 = acc[mt][nt][2] + bb0;
            float v3 = acc[mt][nt][3] + bb1;
            if (do_relu) {
                v0 = fmaxf(v0, 0.f); v1 = fmaxf(v1, 0.f);
                v2 = fmaxf(v2, 0.f); v3 = fmaxf(v3, 0.f);
            }
            if (out_bf) {
                *reinterpret_cast<unsigned*>(Cb + (size_t)gr * Nout + gc)       = pk(v0, v1);
                *reinterpret_cast<unsigned*>(Cb + (size_t)(gr + 8) * Nout + gc) = pk(v2, v3);
            } else {
                *reinterpret_cast<float2*>(C + (size_t)gr * Nout + gc)       = make_float2(v0, v1);
                *reinterpret_cast<float2*>(C + (size_t)(gr + 8) * Nout + gc) = make_float2(v2, v3);
            }
        }
    }
}

// ========== fused edge GEMM (bf16) + msg-cvt + time-enc + attention + scatter ==========
// A k-layout: [0,172) msg (cvt from fp32 input in-stage), [172,176) 0,
// [176,304) te (computed in-stage), [304,320) 0. Matches g_we_bf.
__global__ __launch_bounds__(256) void gemm_attn(
    const float* __restrict__ edge_msg,
    const int* __restrict__ edge_idx, const float* __restrict__ edge_t,
    const float* __restrict__ te_w, const float* __restrict__ te_b)
{
    extern __shared__ unsigned dynsmem[];
    unsigned* As32 = dynsmem;
    unsigned* Ws32 = dynsmem + STG * TBM * WPR;
    const uint32_t sb_a = (uint32_t)__cvta_generic_to_shared(dynsmem);
    const uint32_t sb_w = sb_a + STG * TBM * KPADH * 2;

    __shared__ int   sSrc[128];
    __shared__ int   sDst[128];
    __shared__ float sPart[4][128];
    __shared__ float sX[128];

    const int t    = threadIdx.x;
    const int warp = t >> 5;
    const int lane = t & 31;
    const int g    = lane >> 2;
    const int tig  = lane & 3;
    const int wm   = warp >> 2;
    const int wn   = warp & 3;
    const int h    = blockIdx.x;
    const int row0 = blockIdx.y * TBM;
    const int col0 = h * 128;

    if (t < 128) {
        sSrc[t] = edge_idx[row0 + t];
        sDst[t] = edge_idx[EE + row0 + t];
    }

    float acc[4][4][4];
    #pragma unroll
    for (int i = 0; i < 4; i++)
        #pragma unroll
        for (int j = 0; j < 4; j++)
            #pragma unroll
            for (int c = 0; c < 4; c++) acc[i][j][c] = 0.f;

    const int r  = t >> 1;
    const int ch = t & 1;

    auto issue = [&](int s, int k0) {
        int kb = k0 + ch * 8;
        int gr = row0 + r;
        unsigned* ap = &As32[(s * TBM + r) * WPR + ch * 4];
        if (kb < ATT_TE0) {
            // msg columns: load fp32, convert, STS (boundary chunk guarded)
            const float* mp = edge_msg + (size_t)gr * MSGD + kb;
            if (kb < 168) {
                float4 a4 = *(const float4*)(mp);
                float4 b4 = *(const float4*)(mp + 4);
                ap[0] = pk(a4.x, a4.y); ap[1] = pk(a4.z, a4.w);
                ap[2] = pk(b4.x, b4.y); ap[3] = pk(b4.z, b4.w);
            } else {          // kb == 168: cols 168..171 real, 172..175 zero
                float4 a4 = *(const float4*)(mp);
                ap[0] = pk(a4.x, a4.y); ap[1] = pk(a4.z, a4.w);
                ap[2] = 0u; ap[3] = 0u;
            }
        } else if (kb < ATT_TE0 + TDD) {
            float rel = g_lu[edge_idx[gr]] - edge_t[gr];
            int c = kb - ATT_TE0;
            ap[0] = pk(cosf(rel * te_w[c + 0] + te_b[c + 0]),
                       cosf(rel * te_w[c + 1] + te_b[c + 1]));
            ap[1] = pk(cosf(rel * te_w[c + 2] + te_b[c + 2]),
                       cosf(rel * te_w[c + 3] + te_b[c + 3]));
            ap[2] = pk(cosf(rel * te_w[c + 4] + te_b[c + 4]),
                       cosf(rel * te_w[c + 5] + te_b[c + 5]));
            ap[3] = pk(cosf(rel * te_w[c + 6] + te_b[c + 6]),
                       cosf(rel * te_w[c + 7] + te_b[c + 7]));
        } else {
            ap[0] = 0u; ap[1] = 0u; ap[2] = 0u; ap[3] = 0u;
        }
        uint32_t off = (uint32_t)(((s * TBM + r) * KPADH + ch * 8) * 2);
        cp16(sb_w + off, g_we_bf + (size_t)(col0 + r) * K_ATT + kb);
    };
    auto compute = [&](int buf) {
        unsigned af[4][4], bf[4][2];
        #pragma unroll
        for (int mt = 0; mt < 4; mt++) {
            int rb = (buf * TBM) + wm * 64 + mt * 16;
            af[mt][0] = As32[(rb + g    ) * WPR + tig];
            af[mt][1] = As32[(rb + g + 8) * WPR + tig];
            af[mt][2] = As32[(rb + g    ) * WPR + tig + 4];
            af[mt][3] = As32[(rb + g + 8) * WPR + tig + 4];
        }
        #pragma unroll
        for (int nt = 0; nt < 4; nt++) {
            int nb = (buf * TBN) + wn * 32 + nt * 8;
            bf[nt][0] = Ws32[(nb + g) * WPR + tig];
            bf[nt][1] = Ws32[(nb + g) * WPR + tig + 4];
        }
        #pragma unroll
        for (int mt = 0; mt < 4; mt++)
            #pragma unroll
            for (int nt = 0; nt < 4; nt++)
                MMA_BF16(acc[mt][nt], af[mt], bf[nt]);
    };

    const int ktiles = K_ATT / TBK;   // 20
    issue(0, 0);       CP_COMMIT;
    issue(1, TBK);     CP_COMMIT;
    issue(2, 2 * TBK); CP_COMMIT;
    int fetch = 3;
    for (int j = 0; j < ktiles; j++) {
        CP_WAIT2;
        __syncthreads();
        compute(j % STG);
        if (fetch < ktiles) { issue(fetch % STG, fetch * TBK); fetch++; }
        CP_COMMIT;
    }

    // ---- epilogue: logits q.(k+ep), bf16 gathers ----
    const int hoff = h * 128;
    float part[4][2];
    #pragma unroll
    for (int mt = 0; mt < 4; mt++) { part[mt][0] = 0.f; part[mt][1] = 0.f; }

    #pragma unroll
    for (int mt = 0; mt < 4; mt++) {
        int r1 = wm * 64 + mt * 16 + g;
        int r2 = r1 + 8;
        int d1 = sDst[r1], s1 = sSrc[r1];
        int d2 = sDst[r2], s2 = sSrc[r2];
        #pragma unroll
        for (int nt = 0; nt < 4; nt++) {
            int cl = hoff + wn * 32 + nt * 8 + tig * 2;
            float2 q1 = bf2f(*(const unsigned*)(g_qkvbf + (size_t)d1 * 1024 + cl));
            float2 k1 = bf2f(*(const unsigned*)(g_qkvbf + (size_t)s1 * 1024 + 256 + cl));
            float2 q2 = bf2f(*(const unsigned*)(g_qkvbf + (size_t)d2 * 1024 + cl));
            float2 k2 = bf2f(*(const unsigned*)(g_qkvbf + (size_t)s2 * 1024 + 256 + cl));
            part[mt][0] += q1.x * (k1.x + acc[mt][nt][0]) + q1.y * (k1.y + acc[mt][nt][1]);
            part[mt][1] += q2.x * (k2.x + acc[mt][nt][2]) + q2.y * (k2.y + acc[mt][nt][3]);
        }
    }
    #pragma unroll
    for (int mt = 0; mt < 4; mt++) {
        #pragma unroll
        for (int half = 0; half < 2; half++) {
            float p = part[mt][half];
            p += __shfl_xor_sync(0xffffffffu, p, 1);
            p += __shfl_xor_sync(0xffffffffu, p, 2);
            part[mt][half] = p;
        }
    }
    if (tig == 0) {
        #pragma unroll
        for (int mt = 0; mt < 4; mt++) {
            sPart[wn][wm * 64 + mt * 16 + g]     = part[mt][0];
            sPart[wn][wm * 64 + mt * 16 + g + 8] = part[mt][1];
        }
    }
    __syncthreads();

    if (t < 128) {
        const float scal = 0.08838834764831845f;   // 1/sqrt(128)
        float a = sPart[0][t] + sPart[1][t] + sPart[2][t] + sPart[3][t];
        float x = expf(a * scal);
        sX[t] = x;
        atomicAdd(&g_denom[2 * sDst[t] + h], x);
    }
    __syncthreads();

    #pragma unroll
    for (int mt = 0; mt < 4; mt++) {
        int r1 = wm * 64 + mt * 16 + g;
        int r2 = r1 + 8;
        int d1 = sDst[r1], s1 = sSrc[r1];
        int d2 = sDst[r2], s2 = sSrc[r2];
        float x1 = sX[r1], x2 = sX[r2];
        #pragma unroll
        for (int nt = 0; nt < 4; nt++) {
            int cl = hoff + wn * 32 + nt * 8 + tig * 2;
            float2 v1 = bf2f(*(const unsigned*)(g_qkvbf + (size_t)s1 * 1024 + 512 + cl));
            float2 v2 = bf2f(*(const unsigned*)(g_qkvbf + (size_t)s2 * 1024 + 512 + cl));
            atomicAdd((float2*)(g_agg + (size_t)d1 * 256 + cl),
                      make_float2((v1.x + acc[mt][nt][0]) * x1,
                                  (v1.y + acc[mt][nt][1]) * x1));
            atomicAdd((float2*)(g_agg + (size_t)d2 * 256 + cl),
                      make_float2((v2.x + acc[mt][nt][2]) * x2,
                                  (v2.y + acc[mt][nt][3]) * x2));
        }
    }
}

// ---------------- weight conversion (once per launch) ----------------
__global__ void k_cvtw(
    const float* __restrict__ w_ih, const float* __restrict__ w_hh,
    const float* __restrict__ Wq, const float* __restrict__ Wk,
    const float* __restrict__ Wv, const float* __restrict__ Wskip,
    const float* __restrict__ We, const float* __restrict__ lp_hw)
{
    int seg = blockIdx.y;
    int idx = blockIdx.x * 256 + threadIdx.x;
    if (seg == 0) {                       // gru_w_ih: [768][812] -> [768][816]
        if (idx < 768 * K_GI) {
            int rr = idx / K_GI, c = idx % K_GI;
            g_wih_bf[idx] = __float2bfloat16(c < GRUIN ? w_ih[rr * GRUIN + c] : 0.f);
        }
    } else if (seg == 1) {
        if (idx < 768 * 256) g_whh_bf[idx] = __float2bfloat16(w_hh[idx]);
    } else if (seg == 2) {
        if (idx < 256 * 256) g_wq_bf[idx] = __float2bfloat16(Wq[idx]);
    } else if (seg == 3) {
        if (idx < 256 * 256) g_wk_bf[idx] = __float2bfloat16(Wk[idx]);
    } else if (seg == 4) {
        if (idx < 256 * 256) g_wv_bf[idx] = __float2bfloat16(Wv[idx]);
    } else if (seg == 5) {
        if (idx < 256 * 256) g_ws_bf[idx] = __float2bfloat16(Wskip[idx]);
    } else if (seg == 6) {                // We: [256][300] -> padded [256][320]
        if (idx < 256 * K_ATT) {
            int rr = idx / K_ATT, c = idx % K_ATT;
            float v = 0.f;
            if (c < MSGD)                               v = We[rr * 300 + c];
            else if (c >= ATT_TE0 && c < ATT_TE0 + TDD) v = We[rr * 300 + (c - 4)];
            g_we_bf[idx] = __float2bfloat16(v);
        }
    } else {
        if (idx < 256 * 512) g_lph_bf[idx] = __float2bfloat16(lp_hw[idx]);
    }
}

// ---------------- zero atomic accumulators ----------------
__global__ void k_zero()
{
    int i = blockIdx.x * blockDim.x + threadIdx.x;
    float4 z = make_float4(0.f, 0.f, 0.f, 0.f);
    if (i < NN * 64) ((float4*)g_agg)[i] = z;
    if (i < NN / 2)  ((float4*)g_denom)[i] = z;
}

// ---------------- build GRU input (bf16), warp per node ----------------
__global__ __launch_bounds__(256) void k_build_aggr(
    const int* __restrict__ node_ids, const int* __restrict__ mem_last_update,
    const int* __restrict__ mem_rel_t, const int* __restrict__ mem_dst_id,
    const float* __restrict__ mem_table, const float* __restrict__ mem_msg_table,
    const float* __restrict__ mem_dir,
    const float* __restrict__ te_w, const float* __restrict__ te_b)
{
    const int lane = threadIdx.x & 31;
    const int nwarps = gridDim.x * 8;
    const float4 w4 = ((const float4*)te_w)[lane];
    const float4 b4 = ((const float4*)te_b)[lane];
    for (int n = blockIdx.x * 8 + (threadIdx.x >> 5); n < NN; n += nwarps) {
        const int nid = node_ids[n];
        const int did = mem_dst_id[nid];
        const float d0 = mem_dir[2 * nid], d1 = mem_dir[2 * nid + 1];
        const float4* sm4 = (const float4*)(mem_table + (size_t)nid * MEMD);
        const float4* dm4 = (const float4*)(mem_table + (size_t)did * MEMD);
        __nv_bfloat16* ag = g_aggrbf + (size_t)n * K_GI;
        __nv_bfloat16* hb = g_hbf + (size_t)n * MEMD;
        #pragma unroll
        for (int i = 0; i < 2; i++) {
            int j = lane + i * 32;
            float4 s = sm4[j], d = dm4[j];
            float4 c1 = make_float4(s.x*d0 + d.x*d1, s.y*d0 + d.y*d1,
                                    s.z*d0 + d.z*d1, s.w*d0 + d.w*d1);
            float4 c2 = make_float4(s.x*d1 + d.x*d0, s.y*d1 + d.y*d0,
                                    s.z*d1 + d.z*d0, s.w*d1 + d.w*d0);
            *(uint2*)(ag + 4 * j)       = f4bf(c1);
            *(uint2*)(ag + 256 + 4 * j) = f4bf(c2);
            *(uint2*)(hb + 4 * j)       = f4bf(s);
        }
        const float4* mg = (const float4*)(mem_msg_table + (size_t)nid * MSGD);
        for (int j = lane; j < MSGD / 4; j += 32)
            *(uint2*)(ag + 512 + 4 * j) = f4bf(mg[j]);
        float rt = (float)mem_rel_t[nid];
        float4 te = make_float4(cosf(rt * w4.x + b4.x), cosf(rt * w4.y + b4.y),
                                cosf(rt * w4.z + b4.z), cosf(rt * w4.w + b4.w));
        *(uint2*)(ag + 684 + 4 * lane) = f4bf(te);
        if (lane == 0) {
            *(uint2*)(ag + 812) = make_uint2(0u, 0u);   // zero pad
            g_lu[n] = (float)mem_last_update[nid];
        }
    }
}

// ---------------- GRU gate combine -> bf16 memory ----------------
__global__ void k_gru(const int* __restrict__ node_ids,
                      const float* __restrict__ mem_table)
{
    int i4 = blockIdx.x * blockDim.x + threadIdx.x;
    if (i4 >= NN * 64) return;
    int n = i4 >> 6, c4 = (i4 & 63) * 4;
    const float* gi = g_gi + (size_t)n * G3;
    const float* gh = g_gh + (size_t)n * G3;
    float4 ir = *(const float4*)(gi + c4);
    float4 iz = *(const float4*)(gi + 256 + c4);
    float4 in_ = *(const float4*)(gi + 512 + c4);
    float4 hr = *(const float4*)(gh + c4);
    float4 hz = *(const float4*)(gh + 256 + c4);
    float4 hn = *(const float4*)(gh + 512 + c4);
    float4 hv = *(const float4*)(mem_table + (size_t)node_ids[n] * MEMD + c4);
    float4 o;
    {
        float r = 1.f/(1.f+expf(-(ir.x+hr.x))), z = 1.f/(1.f+expf(-(iz.x+hz.x)));
        o.x = (1.f-z)*tanhf(in_.x + r*hn.x) + z*hv.x;
    }{
        float r = 1.f/(1.f+expf(-(ir.y+hr.y))), z = 1.f/(1.f+expf(-(iz.y+hz.y)));
        o.y = (1.f-z)*tanhf(in_.y + r*hn.y) + z*hv.y;
    }{
        float r = 1.f/(1.f+expf(-(ir.z+hr.z))), z = 1.f/(1.f+expf(-(iz.z+hz.z)));
        o.z = (1.f-z)*tanhf(in_.z + r*hn.z) + z*hv.z;
    }{
        float r = 1.f/(1.f+expf(-(ir.w+hr.w))), z = 1.f/(1.f+expf(-(iz.w+hz.w)));
        o.w = (1.f-z)*tanhf(in_.w + r*hn.w) + z*hv.w;
    }
    *(uint2*)(g_membf + (size_t)n * MEMD + c4) = f4bf(o);
}

// ---------------- z = skip(bf16) + agg/denom -> bf16 ----------------
__global__ void k_zfin()
{
    int i4 = blockIdx.x * blockDim.x + threadIdx.x;
    if (i4 >= NN * 64) return;
    int n = i4 >> 6, c4 = (i4 & 63) * 4;
    float rinv = 1.f / (g_denom[2 * n + (c4 >> 7)] + 1e-16f);
    float4 a = *(const float4*)(g_agg + (size_t)n * 256 + c4);
    uint2 sku = *(const uint2*)(g_qkvbf + (size_t)n * 1024 + 768 + c4);
    float2 s0 = bf2f(sku.x), s1 = bf2f(sku.y);
    float4 z = make_float4(s0.x + a.x * rinv, s0.y + a.y * rinv,
                           s1.x + a.z * rinv, s1.y + a.w * rinv);
    *(uint2*)(g_zbf + (size_t)n * MEMD + c4) = f4bf(z);
}

// ---------------- final dot + mask + sigmoid ----------------
__global__ __launch_bounds__(256) void k_final(
    const int* __restrict__ node_idx, const float* __restrict__ lp_fw,
    const float* __restrict__ lp_fb, float* __restrict__ out)
{
    const int r = blockIdx.x * 8 + (threadIdx.x >> 5);
    const int lane = threadIdx.x & 31;
    if (r >= 2 * BB) return;
    const float4* h4 = (const float4*)(g_hid + (size_t)r * 256);
    const float4* w4 = (const float4*)lp_fw;
    float4 a = h4[lane], b = w4[lane];
    float4 a2 = h4[32 + lane], b2 = w4[32 + lane];
    float s = a.x*b.x + a.y*b.y + a.z*b.z + a.w*b.w
            + a2.x*b2.x + a2.y*b2.y + a2.z*b2.z + a2.w*b2.w;
    #pragma unroll
    for (int o = 16; o; o >>= 1) s += __shfl_xor_sync(0xffffffffu, s, o);
    if (lane == 0) {
        int bidx = r & (BB - 1);
        float mask = (node_idx[bidx] < NN - 1) ? 1.f : 0.f;
        float val = (s + lp_fb[0]) * mask;
        out[r] = 1.f / (1.f + expf(-val));
    }
}

// ---------------- launch ----------------
extern "C" void kernel_launch(void* const* d_in, const int* in_sizes, int n_in,
                              void* d_out, int out_size)
{
    const int*   node_ids        = (const int*)  d_in[0];
    const int*   node_idx        = (const int*)  d_in[1];
    const int*   edge_idx        = (const int*)  d_in[2];
    const int*   mem_last_update = (const int*)  d_in[3];
    const int*   mem_rel_t       = (const int*)  d_in[4];
    const int*   mem_dst_id      = (const int*)  d_in[5];
    const float* edge_t          = (const float*)d_in[6];
    const float* edge_msg        = (const float*)d_in[7];
    const float* mem_table       = (const float*)d_in[8];
    const float* mem_msg_table   = (const float*)d_in[9];
    const float* mem_dir         = (const float*)d_in[10];
    const float* te_mem_w        = (const float*)d_in[11];
    const float* te_mem_b        = (const float*)d_in[12];
    const float* gru_w_ih        = (const float*)d_in[13];
    const float* gru_w_hh        = (const float*)d_in[14];
    const float* gru_b_ih        = (const float*)d_in[15];
    const float* gru_b_hh        = (const float*)d_in[16];
    const float* te_gnn_w        = (const float*)d_in[17];
    const float* te_gnn_b        = (const float*)d_in[18];
    const float* Wq              = (const float*)d_in[19];
    const float* bq              = (const float*)d_in[20];
    const float* Wk              = (const float*)d_in[21];
    const float* bk              = (const float*)d_in[22];
    const float* Wv              = (const float*)d_in[23];
    const float* bv              = (const float*)d_in[24];
    const float* We              = (const float*)d_in[25];
    const float* Wskip           = (const float*)d_in[26];
    const float* bskip           = (const float*)d_in[27];
    const float* lp_hw           = (const float*)d_in[28];
    const float* lp_hb           = (const float*)d_in[29];
    const float* lp_fw           = (const float*)d_in[30];
    const float* lp_fb           = (const float*)d_in[31];

    __nv_bfloat16 *p_aggrbf, *p_hbf, *p_membf, *p_zbf, *p_qkvbf,
                  *p_wih, *p_whh, *p_wq, *p_wk, *p_wv, *p_ws, *p_lph;
    float *p_gi, *p_gh, *p_hid;
    cudaGetSymbolAddress((void**)&p_aggrbf, g_aggrbf);
    cudaGetSymbolAddress((void**)&p_hbf,    g_hbf);
    cudaGetSymbolAddress((void**)&p_membf,  g_membf);
    cudaGetSymbolAddress((void**)&p_zbf,    g_zbf);
    cudaGetSymbolAddress((void**)&p_qkvbf,  g_qkvbf);
    cudaGetSymbolAddress((void**)&p_wih,    g_wih_bf);
    cudaGetSymbolAddress((void**)&p_whh,    g_whh_bf);
    cudaGetSymbolAddress((void**)&p_wq,     g_wq_bf);
    cudaGetSymbolAddress((void**)&p_wk,     g_wk_bf);
    cudaGetSymbolAddress((void**)&p_wv,     g_wv_bf);
    cudaGetSymbolAddress((void**)&p_ws,     g_ws_bf);
    cudaGetSymbolAddress((void**)&p_lph,    g_lph_bf);
    cudaGetSymbolAddress((void**)&p_gi,     g_gi);
    cudaGetSymbolAddress((void**)&p_gh,     g_gh);
    cudaGetSymbolAddress((void**)&p_hid,    g_hid);

    cudaFuncSetAttribute(gemm5<0>, cudaFuncAttributeMaxDynamicSharedMemorySize, SMEM_BYTES);
    cudaFuncSetAttribute(gemm5<2>, cudaFuncAttributeMaxDynamicSharedMemorySize, SMEM_BYTES);
    cudaFuncSetAttribute(gemm5<3>, cudaFuncAttributeMaxDynamicSharedMemorySize, SMEM_BYTES);
    cudaFuncSetAttribute(gemm_attn, cudaFuncAttributeMaxDynamicSharedMemorySize, SMEM_BYTES);

    // ---- conversions + zero ----
    k_zero<<<4096, 256>>>();
    k_cvtw<<<dim3((768 * K_GI + 255) / 256, 8), 256>>>(
        gru_w_ih, gru_w_hh, Wq, Wk, Wv, Wskip, We, lp_hw);

    // ---- memory (GRU) ----
    k_build_aggr<<<2048, 256>>>(node_ids, mem_last_update, mem_rel_t, mem_dst_id,
                                mem_table, mem_msg_table, mem_dir, te_mem_w, te_mem_b);
    gemm5<0><<<dim3(G3 / TBN, NN / TBM), 256, SMEM_BYTES>>>(
        p_aggrbf, K_GI, nullptr,
        p_wih, nullptr, nullptr, nullptr,
        gru_b_ih, nullptr, nullptr, nullptr,
        p_gi, G3, K_GI, 0, 0);
    gemm5<0><<<dim3(G3 / TBN, NN / TBM), 256, SMEM_BYTES>>>(
        p_hbf, 256, nullptr,
        p_whh, nullptr, nullptr, nullptr,
        gru_b_hh, nullptr, nullptr, nullptr,
        p_gh, G3, 256, 0, 0);
    k_gru<<<4096, 256>>>(node_ids, mem_table);

    // ---- fused q|k|v|skip projection (bf16 output) ----
    gemm5<3><<<dim3(1024 / TBN, NN / TBM), 256, SMEM_BYTES>>>(
        p_membf, 256, nullptr,
        p_wq, p_wk, p_wv, p_ws,
        bq, bk, bv, bskip,
        (float*)p_qkvbf, 1024, 256, 0, 1);

    // ---- fused edge projection + msg-cvt + time-enc + attention + scatter ----
    gemm_attn<<<dim3(2, EE / TBM), 256, SMEM_BYTES>>>(
        edge_msg, edge_idx, edge_t, te_gnn_w, te_gnn_b);

    k_zfin<<<4096, 256>>>();

    // ---- link predictor ----
    gemm5<2><<<dim3(256 / TBN, (2 * BB) / TBM), 256, SMEM_BYTES>>>(
        p_zbf, 256, node_idx,
        p_lph, nullptr, nullptr, nullptr,
        lp_hb, nullptr, nullptr, nullptr,
        p_hid, 256, 512, 1, 0);
    k_final<<<1024, 256>>>(node_idx, lp_fw, lp_fb, (float*)d_out);
}

// round 13
// speedup vs baseline: 1.0565x; 1.0565x over previous
#include <cuda_runtime.h>
#include <cuda_bf16.h>
#include <math.h>
#include <stdint.h>

// ---------------- problem constants ----------------
#define NN     16384
#define BB     4096
#define EE     131072
#define MEMD   256
#define TDD    128
#define MSGD   172
#define GRUIN  812
#define G3     768

// padded K dims (multiples of 16 halves -> no k-guards in pipeline)
#define K_GI   816     // 812 real + 4 zero
#define K_ATT  320     // 172 msg + 4 zero + 128 te + 16 zero
#define ATT_TE0 176
#define MSG_STRIDE 176

// ---------------- device scratch ----------------
__device__ __nv_bfloat16 g_aggrbf[(size_t)NN * K_GI];
__device__ __nv_bfloat16 g_hbf   [(size_t)NN * MEMD];
__device__ __nv_bfloat16 g_membf [(size_t)NN * MEMD];
__device__ __nv_bfloat16 g_zbf   [(size_t)NN * MEMD];
__device__ __nv_bfloat16 g_msgbf [(size_t)EE * MSG_STRIDE];
__device__ __nv_bfloat16 g_qkvbf [(size_t)NN * 1024];   // [q | k | v | skip] bf16
__device__ __nv_bfloat16 g_wih_bf[768 * K_GI];
__device__ __nv_bfloat16 g_whh_bf[768 * 256];
__device__ __nv_bfloat16 g_wq_bf [256 * 256];
__device__ __nv_bfloat16 g_wk_bf [256 * 256];
__device__ __nv_bfloat16 g_wv_bf [256 * 256];
__device__ __nv_bfloat16 g_ws_bf [256 * 256];
__device__ __nv_bfloat16 g_we_bf [256 * K_ATT];
__device__ __nv_bfloat16 g_lph_bf[256 * 512];

__device__ float g_lu   [NN];
__device__ float g_gi   [(size_t)NN * G3];
__device__ float g_gh   [(size_t)NN * G3];
__device__ float g_denom[(size_t)NN * 2];
__device__ float g_agg  [(size_t)NN * MEMD];
__device__ float g_hid  [(size_t)2 * BB * 256];

// ---------------- tiles (R9/R11 champion parameters) ----------------
#define TBM 128
#define TBN 128
#define TBK 16
#define KPADH 24
#define WPR 12
#define STG 4
#define SMEM_BYTES (2 * STG * TBM * KPADH * 2)   // 49152

#define MMA_BF16(acc, af, bf)                                              \
    asm volatile(                                                          \
        "mma.sync.aligned.m16n8k16.row.col.f32.bf16.bf16.f32 "             \
        "{%0,%1,%2,%3}, {%4,%5,%6,%7}, {%8,%9}, {%0,%1,%2,%3};"            \
        : "+f"(acc[0]), "+f"(acc[1]), "+f"(acc[2]), "+f"(acc[3])           \
        : "r"(af[0]), "r"(af[1]), "r"(af[2]), "r"(af[3]),                  \
          "r"(bf[0]), "r"(bf[1]))

__device__ __forceinline__ void cp16(uint32_t dst, const void* src) {
    asm volatile("cp.async.cg.shared.global [%0], [%1], 16;"
                 :: "r"(dst), "l"(src));
}
#define CP_COMMIT asm volatile("cp.async.commit_group;")
#define CP_WAIT2  asm volatile("cp.async.wait_group 2;")

__device__ __forceinline__ unsigned pk(float a, float b) {
    unsigned x = (unsigned)__bfloat16_as_ushort(__float2bfloat16(a));
    unsigned y = (unsigned)__bfloat16_as_ushort(__float2bfloat16(b));
    return x | (y << 16);
}
__device__ __forceinline__ uint2 f4bf(float4 v) {
    return make_uint2(pk(v.x, v.y), pk(v.z, v.w));
}
__device__ __forceinline__ float2 bf2f(unsigned u) {
    __nv_bfloat162 h = *reinterpret_cast<__nv_bfloat162*>(&u);
    return __bfloat1622float2(h);
}
__device__ __forceinline__ float fsig(float x) {   // fast sigmoid
    return 1.f / (1.f + __expf(-x));
}

// ================= bf16 cp.async tensor GEMM =================
// MODE 0: plain bf16 A. MODE 2: link-pred pair gather. MODE 3: 4 stacked W.
// out_bf != 0 -> pack outputs to bf16 (C reinterpreted).
template<int MODE>
__global__ __launch_bounds__(256) void gemm5(
    const __nv_bfloat16* __restrict__ A, int strideA,
    const int* __restrict__ gidx,
    const __nv_bfloat16* __restrict__ W0c, const __nv_bfloat16* __restrict__ W1c,
    const __nv_bfloat16* __restrict__ W2c, const __nv_bfloat16* __restrict__ W3c,
    const float* __restrict__ b0c, const float* __restrict__ b1c,
    const float* __restrict__ b2c, const float* __restrict__ b3c,
    float* __restrict__ C, int Nout, int K, int do_relu, int out_bf)
{
    extern __shared__ unsigned dynsmem[];
    unsigned* As32 = dynsmem;                      // [STG][128][WPR]
    unsigned* Ws32 = dynsmem + STG * TBM * WPR;
    const uint32_t sb_a = (uint32_t)__cvta_generic_to_shared(dynsmem);
    const uint32_t sb_w = sb_a + STG * TBM * KPADH * 2;

    const int t    = threadIdx.x;
    const int warp = t >> 5;
    const int lane = t & 31;
    const int g    = lane >> 2;
    const int tig  = lane & 3;
    const int wm   = warp >> 2;
    const int wn   = warp & 3;
    const int row0 = blockIdx.y * TBM;
    const int col0 = blockIdx.x * TBN;

    const __nv_bfloat16* Wsel = W0c;
    const float* bsel = b0c;
    int colL = col0;
    if (MODE == 3) {
        int grp = col0 >> 8;
        Wsel = (grp == 0) ? W0c : (grp == 1) ? W1c : (grp == 2) ? W2c : W3c;
        bsel = (grp == 0) ? b0c : (grp == 1) ? b1c : (grp == 2) ? b2c : b3c;
        colL = col0 & 255;
    }

    float acc[4][4][4];
    #pragma unroll
    for (int i = 0; i < 4; i++)
        #pragma unroll
        for (int j = 0; j < 4; j++)
            #pragma unroll
            for (int c = 0; c < 4; c++) acc[i][j][c] = 0.f;

    const int r  = t >> 1;
    const int ch = t & 1;

    auto issue = [&](int s, int k0) {
        int kb = k0 + ch * 8;
        const __nv_bfloat16* srcA;
        if (MODE == 2) {
            int gr = row0 + r;
            int b = gr & (BB - 1), side = gr >> 12;
            if (kb < 256) srcA = A + (size_t)gidx[b] * 256 + kb;
            else          srcA = A + (size_t)gidx[BB + side * BB + b] * 256 + (kb - 256);
        } else {
            srcA = A + (size_t)(row0 + r) * strideA + kb;
        }
        uint32_t off = (uint32_t)(((s * TBM + r) * KPADH + ch * 8) * 2);
        cp16(sb_a + off, srcA);
        cp16(sb_w + off, Wsel + (size_t)(colL + r) * K + kb);
    };
    auto compute = [&](int buf) {
        unsigned af[4][4], bf[4][2];
        #pragma unroll
        for (int mt = 0; mt < 4; mt++) {
            int rb = (buf * TBM) + wm * 64 + mt * 16;
            af[mt][0] = As32[(rb + g    ) * WPR + tig];
            af[mt][1] = As32[(rb + g + 8) * WPR + tig];
            af[mt][2] = As32[(rb + g    ) * WPR + tig + 4];
            af[mt][3] = As32[(rb + g + 8) * WPR + tig + 4];
        }
        #pragma unroll
        for (int nt = 0; nt < 4; nt++) {
            int nb = (buf * TBN) + wn * 32 + nt * 8;
            bf[nt][0] = Ws32[(nb + g) * WPR + tig];
            bf[nt][1] = Ws32[(nb + g) * WPR + tig + 4];
        }
        #pragma unroll
        for (int mt = 0; mt < 4; mt++)
            #pragma unroll
            for (int nt = 0; nt < 4; nt++)
                MMA_BF16(acc[mt][nt], af[mt], bf[nt]);
    };

    const int ktiles = K / TBK;
    issue(0, 0);       CP_COMMIT;
    issue(1, TBK);     CP_COMMIT;
    issue(2, 2 * TBK); CP_COMMIT;
    int fetch = 3;
    for (int j = 0; j < ktiles; j++) {
        CP_WAIT2;
        __syncthreads();
        compute(j % STG);
        if (fetch < ktiles) { issue(fetch % STG, fetch * TBK); fetch++; }
        CP_COMMIT;
    }

    __nv_bfloat16* Cb = reinterpret_cast<__nv_bfloat16*>(C);
    #pragma unroll
    for (int mt = 0; mt < 4; mt++) {
        int gr = row0 + wm * 64 + mt * 16 + g;
        #pragma unroll
        for (int nt = 0; nt < 4; nt++) {
            int nl = colL + wn * 32 + nt * 8 + tig * 2;
            int gc = col0 + wn * 32 + nt * 8 + tig * 2;
            float bb0 = bsel ? bsel[nl]     : 0.f;
            float bb1 = bsel ? bsel[nl + 1] : 0.f;
            float v0 = acc[mt][nt][0] + bb0;
            float v1 = acc[mt][nt][1] + bb1;
            float v2 = acc[mt][nt][2] + bb0;
            float v3 = acc[mt][nt][3] + bb1;
            if (do_relu) {
                v0 = fmaxf(v0, 0.f); v1 = fmaxf(v1, 0.f);
                v2 = fmaxf(v2, 0.f); v3 = fmaxf(v3, 0.f);
            }
            if (out_bf) {
                *reinterpret_cast<unsigned*>(Cb + (size_t)gr * Nout + gc)       = pk(v0, v1);
                *reinterpret_cast<unsigned*>(Cb + (size_t)(gr + 8) * Nout + gc) = pk(v2, v3);
            } else {
                *reinterpret_cast<float2*>(C + (size_t)gr * Nout + gc)       = make_float2(v0, v1);
                *reinterpret_cast<float2*>(C + (size_t)(gr + 8) * Nout + gc) = make_float2(v2, v3);
            }
        }
    }
}

// ========== fused edge GEMM (bf16) + time-enc + attention + scatter ==========
__global__ __launch_bounds__(256) void gemm_attn(
    const int* __restrict__ edge_idx, const float* __restrict__ edge_t,
    const float* __restrict__ te_w, const float* __restrict__ te_b)
{
    extern __shared__ unsigned dynsmem[];
    unsigned* As32 = dynsmem;
    unsigned* Ws32 = dynsmem + STG * TBM * WPR;
    const uint32_t sb_a = (uint32_t)__cvta_generic_to_shared(dynsmem);
    const uint32_t sb_w = sb_a + STG * TBM * KPADH * 2;

    __shared__ int   sSrc[128];
    __shared__ int   sDst[128];
    __shared__ float sPart[4][128];
    __shared__ float sX[128];

    const int t    = threadIdx.x;
    const int warp = t >> 5;
    const int lane = t & 31;
    const int g    = lane >> 2;
    const int tig  = lane & 3;
    const int wm   = warp >> 2;
    const int wn   = warp & 3;
    const int h    = blockIdx.x;
    const int row0 = blockIdx.y * TBM;
    const int col0 = h * 128;

    if (t < 128) {
        sSrc[t] = edge_idx[row0 + t];
        sDst[t] = edge_idx[EE + row0 + t];
    }

    float acc[4][4][4];
    #pragma unroll
    for (int i = 0; i < 4; i++)
        #pragma unroll
        for (int j = 0; j < 4; j++)
            #pragma unroll
            for (int c = 0; c < 4; c++) acc[i][j][c] = 0.f;

    const int r  = t >> 1;
    const int ch = t & 1;

    auto issue = [&](int s, int k0) {
        int kb = k0 + ch * 8;
        int gr = row0 + r;
        uint32_t off = (uint32_t)(((s * TBM + r) * KPADH + ch * 8) * 2);
        unsigned* ap = &As32[(s * TBM + r) * WPR + ch * 4];
        if (kb < MSG_STRIDE) {
            cp16(sb_a + off, g_msgbf + (size_t)gr * MSG_STRIDE + kb);
        } else if (kb < ATT_TE0 + TDD) {
            float rel = g_lu[edge_idx[gr]] - edge_t[gr];
            int c = kb - ATT_TE0;
            ap[0] = pk(__cosf(rel * te_w[c + 0] + te_b[c + 0]),
                       __cosf(rel * te_w[c + 1] + te_b[c + 1]));
            ap[1] = pk(__cosf(rel * te_w[c + 2] + te_b[c + 2]),
                       __cosf(rel * te_w[c + 3] + te_b[c + 3]));
            ap[2] = pk(__cosf(rel * te_w[c + 4] + te_b[c + 4]),
                       __cosf(rel * te_w[c + 5] + te_b[c + 5]));
            ap[3] = pk(__cosf(rel * te_w[c + 6] + te_b[c + 6]),
                       __cosf(rel * te_w[c + 7] + te_b[c + 7]));
        } else {
            ap[0] = 0u; ap[1] = 0u; ap[2] = 0u; ap[3] = 0u;
        }
        cp16(sb_w + off, g_we_bf + (size_t)(col0 + r) * K_ATT + kb);
    };
    auto compute = [&](int buf) {
        unsigned af[4][4], bf[4][2];
        #pragma unroll
        for (int mt = 0; mt < 4; mt++) {
            int rb = (buf * TBM) + wm * 64 + mt * 16;
            af[mt][0] = As32[(rb + g    ) * WPR + tig];
            af[mt][1] = As32[(rb + g + 8) * WPR + tig];
            af[mt][2] = As32[(rb + g    ) * WPR + tig + 4];
            af[mt][3] = As32[(rb + g + 8) * WPR + tig + 4];
        }
        #pragma unroll
        for (int nt = 0; nt < 4; nt++) {
            int nb = (buf * TBN) + wn * 32 + nt * 8;
            bf[nt][0] = Ws32[(nb + g) * WPR + tig];
            bf[nt][1] = Ws32[(nb + g) * WPR + tig + 4];
        }
        #pragma unroll
        for (int mt = 0; mt < 4; mt++)
            #pragma unroll
            for (int nt = 0; nt < 4; nt++)
                MMA_BF16(acc[mt][nt], af[mt], bf[nt]);
    };

    const int ktiles = K_ATT / TBK;   // 20
    issue(0, 0);       CP_COMMIT;
    issue(1, TBK);     CP_COMMIT;
    issue(2, 2 * TBK); CP_COMMIT;
    int fetch = 3;
    for (int j = 0; j < ktiles; j++) {
        CP_WAIT2;
        __syncthreads();
        compute(j % STG);
        if (fetch < ktiles) { issue(fetch % STG, fetch * TBK); fetch++; }
        CP_COMMIT;
    }

    // ---- epilogue: logits q.(k+ep), bf16 gathers ----
    const int hoff = h * 128;
    float part[4][2];
    #pragma unroll
    for (int mt = 0; mt < 4; mt++) { part[mt][0] = 0.f; part[mt][1] = 0.f; }

    #pragma unroll
    for (int mt = 0; mt < 4; mt++) {
        int r1 = wm * 64 + mt * 16 + g;
        int r2 = r1 + 8;
        int d1 = sDst[r1], s1 = sSrc[r1];
        int d2 = sDst[r2], s2 = sSrc[r2];
        #pragma unroll
        for (int nt = 0; nt < 4; nt++) {
            int cl = hoff + wn * 32 + nt * 8 + tig * 2;
            float2 q1 = bf2f(*(const unsigned*)(g_qkvbf + (size_t)d1 * 1024 + cl));
            float2 k1 = bf2f(*(const unsigned*)(g_qkvbf + (size_t)s1 * 1024 + 256 + cl));
            float2 q2 = bf2f(*(const unsigned*)(g_qkvbf + (size_t)d2 * 1024 + cl));
            float2 k2 = bf2f(*(const unsigned*)(g_qkvbf + (size_t)s2 * 1024 + 256 + cl));
            part[mt][0] += q1.x * (k1.x + acc[mt][nt][0]) + q1.y * (k1.y + acc[mt][nt][1]);
            part[mt][1] += q2.x * (k2.x + acc[mt][nt][2]) + q2.y * (k2.y + acc[mt][nt][3]);
        }
    }
    #pragma unroll
    for (int mt = 0; mt < 4; mt++) {
        #pragma unroll
        for (int half = 0; half < 2; half++) {
            float p = part[mt][half];
            p += __shfl_xor_sync(0xffffffffu, p, 1);
            p += __shfl_xor_sync(0xffffffffu, p, 2);
            part[mt][half] = p;
        }
    }
    if (tig == 0) {
        #pragma unroll
        for (int mt = 0; mt < 4; mt++) {
            sPart[wn][wm * 64 + mt * 16 + g]     = part[mt][0];
            sPart[wn][wm * 64 + mt * 16 + g + 8] = part[mt][1];
        }
    }
    __syncthreads();

    if (t < 128) {
        const float scal = 0.08838834764831845f;   // 1/sqrt(128)
        float a = sPart[0][t] + sPart[1][t] + sPart[2][t] + sPart[3][t];
        float x = __expf(a * scal);
        sX[t] = x;
        atomicAdd(&g_denom[2 * sDst[t] + h], x);
    }
    __syncthreads();

    #pragma unroll
    for (int mt = 0; mt < 4; mt++) {
        int r1 = wm * 64 + mt * 16 + g;
        int r2 = r1 + 8;
        int d1 = sDst[r1], s1 = sSrc[r1];
        int d2 = sDst[r2], s2 = sSrc[r2];
        float x1 = sX[r1], x2 = sX[r2];
        #pragma unroll
        for (int nt = 0; nt < 4; nt++) {
            int cl = hoff + wn * 32 + nt * 8 + tig * 2;
            float2 v1 = bf2f(*(const unsigned*)(g_qkvbf + (size_t)s1 * 1024 + 512 + cl));
            float2 v2 = bf2f(*(const unsigned*)(g_qkvbf + (size_t)s2 * 1024 + 512 + cl));
            atomicAdd((float2*)(g_agg + (size_t)d1 * 256 + cl),
                      make_float2((v1.x + acc[mt][nt][0]) * x1,
                                  (v1.y + acc[mt][nt][1]) * x1));
            atomicAdd((float2*)(g_agg + (size_t)d2 * 256 + cl),
                      make_float2((v2.x + acc[mt][nt][2]) * x2,
                                  (v2.y + acc[mt][nt][3]) * x2));
        }
    }
}

// ---------------- weight conversion (once per launch) ----------------
__global__ void k_cvtw(
    const float* __restrict__ w_ih, const float* __restrict__ w_hh,
    const float* __restrict__ Wq, const float* __restrict__ Wk,
    const float* __restrict__ Wv, const float* __restrict__ Wskip,
    const float* __restrict__ We, const float* __restrict__ lp_hw)
{
    int seg = blockIdx.y;
    int idx = blockIdx.x * 256 + threadIdx.x;
    if (seg == 0) {                       // gru_w_ih: [768][812] -> [768][816]
        if (idx < 768 * K_GI) {
            int rr = idx / K_GI, c = idx % K_GI;
            g_wih_bf[idx] = __float2bfloat16(c < GRUIN ? w_ih[rr * GRUIN + c] : 0.f);
        }
    } else if (seg == 1) {
        if (idx < 768 * 256) g_whh_bf[idx] = __float2bfloat16(w_hh[idx]);
    } else if (seg == 2) {
        if (idx < 256 * 256) g_wq_bf[idx] = __float2bfloat16(Wq[idx]);
    } else if (seg == 3) {
        if (idx < 256 * 256) g_wk_bf[idx] = __float2bfloat16(Wk[idx]);
    } else if (seg == 4) {
        if (idx < 256 * 256) g_wv_bf[idx] = __float2bfloat16(Wv[idx]);
    } else if (seg == 5) {
        if (idx < 256 * 256) g_ws_bf[idx] = __float2bfloat16(Wskip[idx]);
    } else if (seg == 6) {                // We: [256][300] -> padded [256][320]
        if (idx < 256 * K_ATT) {
            int rr = idx / K_ATT, c = idx % K_ATT;
            float v = 0.f;
            if (c < MSGD)                               v = We[rr * 300 + c];
            else if (c >= ATT_TE0 && c < ATT_TE0 + TDD) v = We[rr * 300 + (c - 4)];
            g_we_bf[idx] = __float2bfloat16(v);
        }
    } else {
        if (idx < 256 * 512) g_lph_bf[idx] = __float2bfloat16(lp_hw[idx]);
    }
}

// ---------------- edge_msg conversion: [E][172] fp32 -> bf16 [E][176] ----------------
__global__ void k_cvtmsg(const float* __restrict__ edge_msg)
{
    int j = blockIdx.x * 256 + threadIdx.x;   // uint2 units
    if (j >= EE * 44) return;
    int e = j / 44, c = j % 44;
    uint2 o = make_uint2(0u, 0u);
    if (c < 43)
        o = f4bf(*(const float4*)(edge_msg + (size_t)e * MSGD + c * 4));
    *(uint2*)(g_msgbf + (size_t)e * MSG_STRIDE + c * 4) = o;
}

// ---------------- zero atomic accumulators ----------------
__global__ void k_zero()
{
    int i = blockIdx.x * blockDim.x + threadIdx.x;
    float4 z = make_float4(0.f, 0.f, 0.f, 0.f);
    if (i < NN * 64) ((float4*)g_agg)[i] = z;
    if (i < NN / 2)  ((float4*)g_denom)[i] = z;
}

// ---------------- build GRU input (bf16), warp per node ----------------
__global__ __launch_bounds__(256) void k_build_aggr(
    const int* __restrict__ node_ids, const int* __restrict__ mem_last_update,
    const int* __restrict__ mem_rel_t, const int* __restrict__ mem_dst_id,
    const float* __restrict__ mem_table, const float* __restrict__ mem_msg_table,
    const float* __restrict__ mem_dir,
    const float* __restrict__ te_w, const float* __restrict__ te_b)
{
    const int lane = threadIdx.x & 31;
    const int nwarps = gridDim.x * 8;
    const float4 w4 = ((const float4*)te_w)[lane];
    const float4 b4 = ((const float4*)te_b)[lane];
    for (int n = blockIdx.x * 8 + (threadIdx.x >> 5); n < NN; n += nwarps) {
        const int nid = node_ids[n];
        const int did = mem_dst_id[nid];
        const float d0 = mem_dir[2 * nid], d1 = mem_dir[2 * nid + 1];
        const float4* sm4 = (const float4*)(mem_table + (size_t)nid * MEMD);
        const float4* dm4 = (const float4*)(mem_table + (size_t)did * MEMD);
        __nv_bfloat16* ag = g_aggrbf + (size_t)n * K_GI;
        __nv_bfloat16* hb = g_hbf + (size_t)n * MEMD;
        #pragma unroll
        for (int i = 0; i < 2; i++) {
            int j = lane + i * 32;
            float4 s = sm4[j], d = dm4[j];
            float4 c1 = make_float4(s.x*d0 + d.x*d1, s.y*d0 + d.y*d1,
                                    s.z*d0 + d.z*d1, s.w*d0 + d.w*d1);
            float4 c2 = make_float4(s.x*d1 + d.x*d0, s.y*d1 + d.y*d0,
                                    s.z*d1 + d.z*d0, s.w*d1 + d.w*d0);
            *(uint2*)(ag + 4 * j)       = f4bf(c1);
            *(uint2*)(ag + 256 + 4 * j) = f4bf(c2);
            *(uint2*)(hb + 4 * j)       = f4bf(s);
        }
        const float4* mg = (const float4*)(mem_msg_table + (size_t)nid * MSGD);
        for (int j = lane; j < MSGD / 4; j += 32)
            *(uint2*)(ag + 512 + 4 * j) = f4bf(mg[j]);
        float rt = (float)mem_rel_t[nid];
        float4 te = make_float4(__cosf(rt * w4.x + b4.x), __cosf(rt * w4.y + b4.y),
                                __cosf(rt * w4.z + b4.z), __cosf(rt * w4.w + b4.w));
        *(uint2*)(ag + 684 + 4 * lane) = f4bf(te);
        if (lane == 0) {
            *(uint2*)(ag + 812) = make_uint2(0u, 0u);   // zero pad
            g_lu[n] = (float)mem_last_update[nid];
        }
    }
}

// ---------------- GRU gate combine -> bf16 memory ----------------
__global__ void k_gru(const int* __restrict__ node_ids,
                      const float* __restrict__ mem_table)
{
    int i4 = blockIdx.x * blockDim.x + threadIdx.x;
    if (i4 >= NN * 64) return;
    int n = i4 >> 6, c4 = (i4 & 63) * 4;
    const float* gi = g_gi + (size_t)n * G3;
    const float* gh = g_gh + (size_t)n * G3;
    float4 ir = *(const float4*)(gi + c4);
    float4 iz = *(const float4*)(gi + 256 + c4);
    float4 in_ = *(const float4*)(gi + 512 + c4);
    float4 hr = *(const float4*)(gh + c4);
    float4 hz = *(const float4*)(gh + 256 + c4);
    float4 hn = *(const float4*)(gh + 512 + c4);
    float4 hv = *(const float4*)(mem_table + (size_t)node_ids[n] * MEMD + c4);
    float4 o;
    {
        float r = fsig(ir.x + hr.x), z = fsig(iz.x + hz.x);
        o.x = (1.f - z) * tanhf(in_.x + r * hn.x) + z * hv.x;
    }{
        float r = fsig(ir.y + hr.y), z = fsig(iz.y + hz.y);
        o.y = (1.f - z) * tanhf(in_.y + r * hn.y) + z * hv.y;
    }{
        float r = fsig(ir.z + hr.z), z = fsig(iz.z + hz.z);
        o.z = (1.f - z) * tanhf(in_.z + r * hn.z) + z * hv.z;
    }{
        float r = fsig(ir.w + hr.w), z = fsig(iz.w + hz.w);
        o.w = (1.f - z) * tanhf(in_.w + r * hn.w) + z * hv.w;
    }
    *(uint2*)(g_membf + (size_t)n * MEMD + c4) = f4bf(o);
}

// ---------------- z = skip(bf16) + agg/denom -> bf16 ----------------
__global__ void k_zfin()
{
    int i4 = blockIdx.x * blockDim.x + threadIdx.x;
    if (i4 >= NN * 64) return;
    int n = i4 >> 6, c4 = (i4 & 63) * 4;
    float rinv = 1.f / (g_denom[2 * n + (c4 >> 7)] + 1e-16f);
    float4 a = *(const float4*)(g_agg + (size_t)n * 256 + c4);
    uint2 sku = *(const uint2*)(g_qkvbf + (size_t)n * 1024 + 768 + c4);
    float2 s0 = bf2f(sku.x), s1 = bf2f(sku.y);
    float4 z = make_float4(s0.x + a.x * rinv, s0.y + a.y * rinv,
                           s1.x + a.z * rinv, s1.y + a.w * rinv);
    *(uint2*)(g_zbf + (size_t)n * MEMD + c4) = f4bf(z);
}

// ---------------- final dot + mask + sigmoid ----------------
__global__ __launch_bounds__(256) void k_final(
    const int* __restrict__ node_idx, const float* __restrict__ lp_fw,
    const float* __restrict__ lp_fb, float* __restrict__ out)
{
    const int r = blockIdx.x * 8 + (threadIdx.x >> 5);
    const int lane = threadIdx.x & 31;
    if (r >= 2 * BB) return;
    const float4* h4 = (const float4*)(g_hid + (size_t)r * 256);
    const float4* w4 = (const float4*)lp_fw;
    float4 a = h4[lane], b = w4[lane];
    float4 a2 = h4[32 + lane], b2 = w4[32 + lane];
    float s = a.x*b.x + a.y*b.y + a.z*b.z + a.w*b.w
            + a2.x*b2.x + a2.y*b2.y + a2.z*b2.z + a2.w*b2.w;
    #pragma unroll
    for (int o = 16; o; o >>= 1) s += __shfl_xor_sync(0xffffffffu, s, o);
    if (lane == 0) {
        int bidx = r & (BB - 1);
        float mask = (node_idx[bidx] < NN - 1) ? 1.f : 0.f;
        float val = (s + lp_fb[0]) * mask;
        out[r] = fsig(val);
    }
}

// ---------------- launch ----------------
extern "C" void kernel_launch(void* const* d_in, const int* in_sizes, int n_in,
                              void* d_out, int out_size)
{
    const int*   node_ids        = (const int*)  d_in[0];
    const int*   node_idx        = (const int*)  d_in[1];
    const int*   edge_idx        = (const int*)  d_in[2];
    const int*   mem_last_update = (const int*)  d_in[3];
    const int*   mem_rel_t       = (const int*)  d_in[4];
    const int*   mem_dst_id      = (const int*)  d_in[5];
    const float* edge_t          = (const float*)d_in[6];
    const float* edge_msg        = (const float*)d_in[7];
    const float* mem_table       = (const float*)d_in[8];
    const float* mem_msg_table   = (const float*)d_in[9];
    const float* mem_dir         = (const float*)d_in[10];
    const float* te_mem_w        = (const float*)d_in[11];
    const float* te_mem_b        = (const float*)d_in[12];
    const float* gru_w_ih        = (const float*)d_in[13];
    const float* gru_w_hh        = (const float*)d_in[14];
    const float* gru_b_ih        = (const float*)d_in[15];
    const float* gru_b_hh        = (const float*)d_in[16];
    const float* te_gnn_w        = (const float*)d_in[17];
    const float* te_gnn_b        = (const float*)d_in[18];
    const float* Wq              = (const float*)d_in[19];
    const float* bq              = (const float*)d_in[20];
    const float* Wk              = (const float*)d_in[21];
    const float* bk              = (const float*)d_in[22];
    const float* Wv              = (const float*)d_in[23];
    const float* bv              = (const float*)d_in[24];
    const float* We              = (const float*)d_in[25];
    const float* Wskip           = (const float*)d_in[26];
    const float* bskip           = (const float*)d_in[27];
    const float* lp_hw           = (const float*)d_in[28];
    const float* lp_hb           = (const float*)d_in[29];
    const float* lp_fw           = (const float*)d_in[30];
    const float* lp_fb           = (const float*)d_in[31];

    __nv_bfloat16 *p_aggrbf, *p_hbf, *p_membf, *p_zbf, *p_qkvbf,
                  *p_wih, *p_whh, *p_wq, *p_wk, *p_wv, *p_ws, *p_lph;
    float *p_gi, *p_gh, *p_hid;
    cudaGetSymbolAddress((void**)&p_aggrbf, g_aggrbf);
    cudaGetSymbolAddress((void**)&p_hbf,    g_hbf);
    cudaGetSymbolAddress((void**)&p_membf,  g_membf);
    cudaGetSymbolAddress((void**)&p_zbf,    g_zbf);
    cudaGetSymbolAddress((void**)&p_qkvbf,  g_qkvbf);
    cudaGetSymbolAddress((void**)&p_wih,    g_wih_bf);
    cudaGetSymbolAddress((void**)&p_whh,    g_whh_bf);
    cudaGetSymbolAddress((void**)&p_wq,     g_wq_bf);
    cudaGetSymbolAddress((void**)&p_wk,     g_wk_bf);
    cudaGetSymbolAddress((void**)&p_wv,     g_wv_bf);
    cudaGetSymbolAddress((void**)&p_ws,     g_ws_bf);
    cudaGetSymbolAddress((void**)&p_lph,    g_lph_bf);
    cudaGetSymbolAddress((void**)&p_gi,     g_gi);
    cudaGetSymbolAddress((void**)&p_gh,     g_gh);
    cudaGetSymbolAddress((void**)&p_hid,    g_hid);

    cudaFuncSetAttribute(gemm5<0>, cudaFuncAttributeMaxDynamicSharedMemorySize, SMEM_BYTES);
    cudaFuncSetAttribute(gemm5<2>, cudaFuncAttributeMaxDynamicSharedMemorySize, SMEM_BYTES);
    cudaFuncSetAttribute(gemm5<3>, cudaFuncAttributeMaxDynamicSharedMemorySize, SMEM_BYTES);
    cudaFuncSetAttribute(gemm_attn, cudaFuncAttributeMaxDynamicSharedMemorySize, SMEM_BYTES);

    // ---- conversions + zero ----
    k_zero<<<4096, 256>>>();
    k_cvtw<<<dim3((768 * K_GI + 255) / 256, 8), 256>>>(
        gru_w_ih, gru_w_hh, Wq, Wk, Wv, Wskip, We, lp_hw);
    k_cvtmsg<<<(EE * 44 + 255) / 256, 256>>>(edge_msg);

    // ---- memory (GRU) ----
    k_build_aggr<<<2048, 256>>>(node_ids, mem_last_update, mem_rel_t, mem_dst_id,
                                mem_table, mem_msg_table, mem_dir, te_mem_w, te_mem_b);
    gemm5<0><<<dim3(G3 / TBN, NN / TBM), 256, SMEM_BYTES>>>(
        p_aggrbf, K_GI, nullptr,
        p_wih, nullptr, nullptr, nullptr,
        gru_b_ih, nullptr, nullptr, nullptr,
        p_gi, G3, K_GI, 0, 0);
    gemm5<0><<<dim3(G3 / TBN, NN / TBM), 256, SMEM_BYTES>>>(
        p_hbf, 256, nullptr,
        p_whh, nullptr, nullptr, nullptr,
        gru_b_hh, nullptr, nullptr, nullptr,
        p_gh, G3, 256, 0, 0);
    k_gru<<<4096, 256>>>(node_ids, mem_table);

    // ---- fused q|k|v|skip projection (bf16 output) ----
    gemm5<3><<<dim3(1024 / TBN, NN / TBM), 256, SMEM_BYTES>>>(
        p_membf, 256, nullptr,
        p_wq, p_wk, p_wv, p_ws,
        bq, bk, bv, bskip,
        (float*)p_qkvbf, 1024, 256, 0, 1);

    // ---- fused edge projection + time-enc + attention + scatter ----
    gemm_attn<<<dim3(2, EE / TBM), 256, SMEM_BYTES>>>(
        edge_idx, edge_t, te_gnn_w, te_gnn_b);

    k_zfin<<<4096, 256>>>();

    // ---- link predictor ----
    gemm5<2><<<dim3(256 / TBN, (2 * BB) / TBM), 256, SMEM_BYTES>>>(
        p_zbf, 256, node_idx,
        p_lph, nullptr, nullptr, nullptr,
        lp_hb, nullptr, nullptr, nullptr,
        p_hid, 256, 512, 1, 0);
    k_final<<<1024, 256>>>(node_idx, lp_fw, lp_fb, (float*)d_out);
}

// round 14
// speedup vs baseline: 1.0593x; 1.0026x over previous
#include <cuda_runtime.h>
#include <cuda_bf16.h>
#include <math.h>
#include <stdint.h>

// ---------------- problem constants ----------------
#define NN     16384
#define BB     4096
#define EE     131072
#define MEMD   256
#define TDD    128
#define MSGD   172
#define GRUIN  812
#define G3     768

// padded K dims (multiples of 16 halves -> no k-guards in pipeline)
#define K_GI   816     // 812 real + 4 zero
#define K_ATT  320     // 172 msg + 4 zero + 128 te + 16 zero
#define ATT_TE0 176
#define MSG_STRIDE 176

// ---------------- device scratch ----------------
__device__ __nv_bfloat16 g_aggrbf[(size_t)NN * K_GI];
__device__ __nv_bfloat16 g_hbf   [(size_t)NN * MEMD];
__device__ __nv_bfloat16 g_membf [(size_t)NN * MEMD];
__device__ __nv_bfloat16 g_zbf   [(size_t)NN * MEMD];
__device__ __nv_bfloat16 g_msgbf [(size_t)EE * MSG_STRIDE];
__device__ __nv_bfloat16 g_qkvbf [(size_t)NN * 1024];   // [q | k | v | skip] bf16
__device__ __nv_bfloat16 g_wih_bf[768 * K_GI];
__device__ __nv_bfloat16 g_whh_bf[768 * 256];
__device__ __nv_bfloat16 g_wq_bf [256 * 256];
__device__ __nv_bfloat16 g_wk_bf [256 * 256];
__device__ __nv_bfloat16 g_wv_bf [256 * 256];
__device__ __nv_bfloat16 g_ws_bf [256 * 256];
__device__ __nv_bfloat16 g_we_bf [256 * K_ATT];
__device__ __nv_bfloat16 g_lph_bf[256 * 512];

__device__ float g_lu   [NN];
__device__ float g_gi   [(size_t)NN * G3];
__device__ float g_gh   [(size_t)NN * G3];
__device__ float g_denom[(size_t)NN * 2];
__device__ float g_agg  [(size_t)NN * MEMD];
__device__ float g_hid  [(size_t)2 * BB * 256];

// ---------------- tiles (champion parameters) ----------------
#define TBM 128
#define TBN 128
#define TBK 16
#define KPADH 24
#define WPR 12
#define STG 4
#define SMEM_BYTES (2 * STG * TBM * KPADH * 2)   // 49152

#define MMA_BF16(acc, af, bf)                                              \
    asm volatile(                                                          \
        "mma.sync.aligned.m16n8k16.row.col.f32.bf16.bf16.f32 "             \
        "{%0,%1,%2,%3}, {%4,%5,%6,%7}, {%8,%9}, {%0,%1,%2,%3};"            \
        : "+f"(acc[0]), "+f"(acc[1]), "+f"(acc[2]), "+f"(acc[3])           \
        : "r"(af[0]), "r"(af[1]), "r"(af[2]), "r"(af[3]),                  \
          "r"(bf[0]), "r"(bf[1]))

__device__ __forceinline__ void cp16(uint32_t dst, const void* src) {
    asm volatile("cp.async.cg.shared.global [%0], [%1], 16;"
                 :: "r"(dst), "l"(src));
}
#define CP_COMMIT asm volatile("cp.async.commit_group;")
#define CP_WAIT2  asm volatile("cp.async.wait_group 2;")

__device__ __forceinline__ unsigned pk(float a, float b) {
    unsigned x = (unsigned)__bfloat16_as_ushort(__float2bfloat16(a));
    unsigned y = (unsigned)__bfloat16_as_ushort(__float2bfloat16(b));
    return x | (y << 16);
}
__device__ __forceinline__ uint2 f4bf(float4 v) {
    return make_uint2(pk(v.x, v.y), pk(v.z, v.w));
}
__device__ __forceinline__ float2 bf2f(unsigned u) {
    __nv_bfloat162 h = *reinterpret_cast<__nv_bfloat162*>(&u);
    return __bfloat1622float2(h);
}
__device__ __forceinline__ float fsig(float x) {
    return 1.f / (1.f + __expf(-x));
}

// ================= bf16 cp.async tensor GEMM =================
// MODE 0: plain bf16 A. MODE 2: link-pred pair gather. MODE 3: 4 stacked W.
// out_bf != 0 -> pack outputs to bf16 (C reinterpreted).
template<int MODE>
__global__ __launch_bounds__(256) void gemm5(
    const __nv_bfloat16* __restrict__ A, int strideA,
    const int* __restrict__ gidx,
    const __nv_bfloat16* __restrict__ W0c, const __nv_bfloat16* __restrict__ W1c,
    const __nv_bfloat16* __restrict__ W2c, const __nv_bfloat16* __restrict__ W3c,
    const float* __restrict__ b0c, const float* __restrict__ b1c,
    const float* __restrict__ b2c, const float* __restrict__ b3c,
    float* __restrict__ C, int Nout, int K, int do_relu, int out_bf)
{
    extern __shared__ unsigned dynsmem[];
    unsigned* As32 = dynsmem;                      // [STG][128][WPR]
    unsigned* Ws32 = dynsmem + STG * TBM * WPR;
    const uint32_t sb_a = (uint32_t)__cvta_generic_to_shared(dynsmem);
    const uint32_t sb_w = sb_a + STG * TBM * KPADH * 2;

    const int t    = threadIdx.x;
    const int warp = t >> 5;
    const int lane = t & 31;
    const int g    = lane >> 2;
    const int tig  = lane & 3;
    const int wm   = warp >> 2;
    const int wn   = warp & 3;
    const int row0 = blockIdx.y * TBM;
    const int col0 = blockIdx.x * TBN;

    const __nv_bfloat16* Wsel = W0c;
    const float* bsel = b0c;
    int colL = col0;
    if (MODE == 3) {
        int grp = col0 >> 8;
        Wsel = (grp == 0) ? W0c : (grp == 1) ? W1c : (grp == 2) ? W2c : W3c;
        bsel = (grp == 0) ? b0c : (grp == 1) ? b1c : (grp == 2) ? b2c : b3c;
        colL = col0 & 255;
    }

    float acc[4][4][4];
    #pragma unroll
    for (int i = 0; i < 4; i++)
        #pragma unroll
        for (int j = 0; j < 4; j++)
            #pragma unroll
            for (int c = 0; c < 4; c++) acc[i][j][c] = 0.f;

    const int r  = t >> 1;
    const int ch = t & 1;

    auto issue = [&](int s, int k0) {
        int kb = k0 + ch * 8;
        const __nv_bfloat16* srcA;
        if (MODE == 2) {
            int gr = row0 + r;
            int b = gr & (BB - 1), side = gr >> 12;
            if (kb < 256) srcA = A + (size_t)gidx[b] * 256 + kb;
            else          srcA = A + (size_t)gidx[BB + side * BB + b] * 256 + (kb - 256);
        } else {
            srcA = A + (size_t)(row0 + r) * strideA + kb;
        }
        uint32_t off = (uint32_t)(((s * TBM + r) * KPADH + ch * 8) * 2);
        cp16(sb_a + off, srcA);
        cp16(sb_w + off, Wsel + (size_t)(colL + r) * K + kb);
    };
    auto compute = [&](int buf) {
        unsigned af[4][4], bf[4][2];
        #pragma unroll
        for (int mt = 0; mt < 4; mt++) {
            int rb = (buf * TBM) + wm * 64 + mt * 16;
            af[mt][0] = As32[(rb + g    ) * WPR + tig];
            af[mt][1] = As32[(rb + g + 8) * WPR + tig];
            af[mt][2] = As32[(rb + g    ) * WPR + tig + 4];
            af[mt][3] = As32[(rb + g + 8) * WPR + tig + 4];
        }
        #pragma unroll
        for (int nt = 0; nt < 4; nt++) {
            int nb = (buf * TBN) + wn * 32 + nt * 8;
            bf[nt][0] = Ws32[(nb + g) * WPR + tig];
            bf[nt][1] = Ws32[(nb + g) * WPR + tig + 4];
        }
        #pragma unroll
        for (int mt = 0; mt < 4; mt++)
            #pragma unroll
            for (int nt = 0; nt < 4; nt++)
                MMA_BF16(acc[mt][nt], af[mt], bf[nt]);
    };

    const int ktiles = K / TBK;
    issue(0, 0);       CP_COMMIT;
    issue(1, TBK);     CP_COMMIT;
    issue(2, 2 * TBK); CP_COMMIT;
    int fetch = 3;
    for (int j = 0; j < ktiles; j++) {
        CP_WAIT2;
        __syncthreads();
        compute(j % STG);
        if (fetch < ktiles) { issue(fetch % STG, fetch * TBK); fetch++; }
        CP_COMMIT;
    }

    __nv_bfloat16* Cb = reinterpret_cast<__nv_bfloat16*>(C);
    #pragma unroll
    for (int mt = 0; mt < 4; mt++) {
        int gr = row0 + wm * 64 + mt * 16 + g;
        #pragma unroll
        for (int nt = 0; nt < 4; nt++) {
            int nl = colL + wn * 32 + nt * 8 + tig * 2;
            int gc = col0 + wn * 32 + nt * 8 + tig * 2;
            float bb0 = bsel ? bsel[nl]     : 0.f;
            float bb1 = bsel ? bsel[nl + 1] : 0.f;
            float v0 = acc[mt][nt][0] + bb0;
            float v1 = acc[mt][nt][1] + bb1;
            float v2 = acc[mt][nt][2] + bb0;
            float v3 = acc[mt][nt][3] + bb1;
            if (do_relu) {
                v0 = fmaxf(v0, 0.f); v1 = fmaxf(v1, 0.f);
                v2 = fmaxf(v2, 0.f); v3 = fmaxf(v3, 0.f);
            }
            if (out_bf) {
                *reinterpret_cast<unsigned*>(Cb + (size_t)gr * Nout + gc)       = pk(v0, v1);
                *reinterpret_cast<unsigned*>(Cb + (size_t)(gr + 8) * Nout + gc) = pk(v2, v3);
            } else {
                *reinterpret_cast<float2*>(C + (size_t)gr * Nout + gc)       = make_float2(v0, v1);
                *reinterpret_cast<float2*>(C + (size_t)(gr + 8) * Nout + gc) = make_float2(v2, v3);
            }
        }
    }
}

// ========== fused edge GEMM (bf16) + time-enc + attention + scatter ==========
__global__ __launch_bounds__(256) void gemm_attn(
    const int* __restrict__ edge_idx, const float* __restrict__ edge_t,
    const float* __restrict__ te_w, const float* __restrict__ te_b)
{
    extern __shared__ unsigned dynsmem[];
    unsigned* As32 = dynsmem;
    unsigned* Ws32 = dynsmem + STG * TBM * WPR;
    const uint32_t sb_a = (uint32_t)__cvta_generic_to_shared(dynsmem);
    const uint32_t sb_w = sb_a + STG * TBM * KPADH * 2;

    __shared__ int   sSrc[128];
    __shared__ int   sDst[128];
    __shared__ float sPart[4][128];
    __shared__ float sX[128];

    const int t    = threadIdx.x;
    const int warp = t >> 5;
    const int lane = t & 31;
    const int g    = lane >> 2;
    const int tig  = lane & 3;
    const int wm   = warp >> 2;
    const int wn   = warp & 3;
    const int h    = blockIdx.x;
    const int row0 = blockIdx.y * TBM;
    const int col0 = h * 128;

    if (t < 128) {
        sSrc[t] = edge_idx[row0 + t];
        sDst[t] = edge_idx[EE + row0 + t];
    }

    float acc[4][4][4];
    #pragma unroll
    for (int i = 0; i < 4; i++)
        #pragma unroll
        for (int j = 0; j < 4; j++)
            #pragma unroll
            for (int c = 0; c < 4; c++) acc[i][j][c] = 0.f;

    const int r  = t >> 1;
    const int ch = t & 1;

    auto issue = [&](int s, int k0) {
        int kb = k0 + ch * 8;
        int gr = row0 + r;
        uint32_t off = (uint32_t)(((s * TBM + r) * KPADH + ch * 8) * 2);
        unsigned* ap = &As32[(s * TBM + r) * WPR + ch * 4];
        if (kb < MSG_STRIDE) {
            cp16(sb_a + off, g_msgbf + (size_t)gr * MSG_STRIDE + kb);
        } else if (kb < ATT_TE0 + TDD) {
            float rel = g_lu[edge_idx[gr]] - edge_t[gr];
            int c = kb - ATT_TE0;
            ap[0] = pk(__cosf(rel * te_w[c + 0] + te_b[c + 0]),
                       __cosf(rel * te_w[c + 1] + te_b[c + 1]));
            ap[1] = pk(__cosf(rel * te_w[c + 2] + te_b[c + 2]),
                       __cosf(rel * te_w[c + 3] + te_b[c + 3]));
            ap[2] = pk(__cosf(rel * te_w[c + 4] + te_b[c + 4]),
                       __cosf(rel * te_w[c + 5] + te_b[c + 5]));
            ap[3] = pk(__cosf(rel * te_w[c + 6] + te_b[c + 6]),
                       __cosf(rel * te_w[c + 7] + te_b[c + 7]));
        } else {
            ap[0] = 0u; ap[1] = 0u; ap[2] = 0u; ap[3] = 0u;
        }
        cp16(sb_w + off, g_we_bf + (size_t)(col0 + r) * K_ATT + kb);
    };
    auto compute = [&](int buf) {
        unsigned af[4][4], bf[4][2];
        #pragma unroll
        for (int mt = 0; mt < 4; mt++) {
            int rb = (buf * TBM) + wm * 64 + mt * 16;
            af[mt][0] = As32[(rb + g    ) * WPR + tig];
            af[mt][1] = As32[(rb + g + 8) * WPR + tig];
            af[mt][2] = As32[(rb + g    ) * WPR + tig + 4];
            af[mt][3] = As32[(rb + g + 8) * WPR + tig + 4];
        }
        #pragma unroll
        for (int nt = 0; nt < 4; nt++) {
            int nb = (buf * TBN) + wn * 32 + nt * 8;
            bf[nt][0] = Ws32[(nb + g) * WPR + tig];
            bf[nt][1] = Ws32[(nb + g) * WPR + tig + 4];
        }
        #pragma unroll
        for (int mt = 0; mt < 4; mt++)
            #pragma unroll
            for (int nt = 0; nt < 4; nt++)
                MMA_BF16(acc[mt][nt], af[mt], bf[nt]);
    };

    const int ktiles = K_ATT / TBK;   // 20
    issue(0, 0);       CP_COMMIT;
    issue(1, TBK);     CP_COMMIT;
    issue(2, 2 * TBK); CP_COMMIT;
    int fetch = 3;
    for (int j = 0; j < ktiles; j++) {
        CP_WAIT2;
        __syncthreads();
        compute(j % STG);
        if (fetch < ktiles) { issue(fetch % STG, fetch * TBK); fetch++; }
        CP_COMMIT;
    }

    // ---- epilogue: logits q.(k+ep), bf16 gathers ----
    const int hoff = h * 128;
    float part[4][2];
    #pragma unroll
    for (int mt = 0; mt < 4; mt++) { part[mt][0] = 0.f; part[mt][1] = 0.f; }

    #pragma unroll
    for (int mt = 0; mt < 4; mt++) {
        int r1 = wm * 64 + mt * 16 + g;
        int r2 = r1 + 8;
        int d1 = sDst[r1], s1 = sSrc[r1];
        int d2 = sDst[r2], s2 = sSrc[r2];
        #pragma unroll
        for (int nt = 0; nt < 4; nt++) {
            int cl = hoff + wn * 32 + nt * 8 + tig * 2;
            float2 q1 = bf2f(*(const unsigned*)(g_qkvbf + (size_t)d1 * 1024 + cl));
            float2 k1 = bf2f(*(const unsigned*)(g_qkvbf + (size_t)s1 * 1024 + 256 + cl));
            float2 q2 = bf2f(*(const unsigned*)(g_qkvbf + (size_t)d2 * 1024 + cl));
            float2 k2 = bf2f(*(const unsigned*)(g_qkvbf + (size_t)s2 * 1024 + 256 + cl));
            part[mt][0] += q1.x * (k1.x + acc[mt][nt][0]) + q1.y * (k1.y + acc[mt][nt][1]);
            part[mt][1] += q2.x * (k2.x + acc[mt][nt][2]) + q2.y * (k2.y + acc[mt][nt][3]);
        }
    }
    #pragma unroll
    for (int mt = 0; mt < 4; mt++) {
        #pragma unroll
        for (int half = 0; half < 2; half++) {
            float p = part[mt][half];
            p += __shfl_xor_sync(0xffffffffu, p, 1);
            p += __shfl_xor_sync(0xffffffffu, p, 2);
            part[mt][half] = p;
        }
    }
    if (tig == 0) {
        #pragma unroll
        for (int mt = 0; mt < 4; mt++) {
            sPart[wn][wm * 64 + mt * 16 + g]     = part[mt][0];
            sPart[wn][wm * 64 + mt * 16 + g + 8] = part[mt][1];
        }
    }
    __syncthreads();

    if (t < 128) {
        const float scal = 0.08838834764831845f;   // 1/sqrt(128)
        float a = sPart[0][t] + sPart[1][t] + sPart[2][t] + sPart[3][t];
        float x = __expf(a * scal);
        sX[t] = x;
        atomicAdd(&g_denom[2 * sDst[t] + h], x);
    }
    __syncthreads();

    #pragma unroll
    for (int mt = 0; mt < 4; mt++) {
        int r1 = wm * 64 + mt * 16 + g;
        int r2 = r1 + 8;
        int d1 = sDst[r1], s1 = sSrc[r1];
        int d2 = sDst[r2], s2 = sSrc[r2];
        float x1 = sX[r1], x2 = sX[r2];
        #pragma unroll
        for (int nt = 0; nt < 4; nt++) {
            int cl = hoff + wn * 32 + nt * 8 + tig * 2;
            float2 v1 = bf2f(*(const unsigned*)(g_qkvbf + (size_t)s1 * 1024 + 512 + cl));
            float2 v2 = bf2f(*(const unsigned*)(g_qkvbf + (size_t)s2 * 1024 + 512 + cl));
            atomicAdd((float2*)(g_agg + (size_t)d1 * 256 + cl),
                      make_float2((v1.x + acc[mt][nt][0]) * x1,
                                  (v1.y + acc[mt][nt][1]) * x1));
            atomicAdd((float2*)(g_agg + (size_t)d2 * 256 + cl),
                      make_float2((v2.x + acc[mt][nt][2]) * x2,
                                  (v2.y + acc[mt][nt][3]) * x2));
        }
    }
}

// ---------------- weight conversion (once per launch) ----------------
__global__ void k_cvtw(
    const float* __restrict__ w_ih, const float* __restrict__ w_hh,
    const float* __restrict__ Wq, const float* __restrict__ Wk,
    const float* __restrict__ Wv, const float* __restrict__ Wskip,
    const float* __restrict__ We, const float* __restrict__ lp_hw)
{
    int seg = blockIdx.y;
    int idx = blockIdx.x * 256 + threadIdx.x;
    if (seg == 0) {                       // gru_w_ih: [768][812] -> [768][816]
        if (idx < 768 * K_GI) {
            int rr = idx / K_GI, c = idx % K_GI;
            g_wih_bf[idx] = __float2bfloat16(c < GRUIN ? w_ih[rr * GRUIN + c] : 0.f);
        }
    } else if (seg == 1) {
        if (idx < 768 * 256) g_whh_bf[idx] = __float2bfloat16(w_hh[idx]);
    } else if (seg == 2) {
        if (idx < 256 * 256) g_wq_bf[idx] = __float2bfloat16(Wq[idx]);
    } else if (seg == 3) {
        if (idx < 256 * 256) g_wk_bf[idx] = __float2bfloat16(Wk[idx]);
    } else if (seg == 4) {
        if (idx < 256 * 256) g_wv_bf[idx] = __float2bfloat16(Wv[idx]);
    } else if (seg == 5) {
        if (idx < 256 * 256) g_ws_bf[idx] = __float2bfloat16(Wskip[idx]);
    } else if (seg == 6) {                // We: [256][300] -> padded [256][320]
        if (idx < 256 * K_ATT) {
            int rr = idx / K_ATT, c = idx % K_ATT;
            float v = 0.f;
            if (c < MSGD)                               v = We[rr * 300 + c];
            else if (c >= ATT_TE0 && c < ATT_TE0 + TDD) v = We[rr * 300 + (c - 4)];
            g_we_bf[idx] = __float2bfloat16(v);
        }
    } else {
        if (idx < 256 * 512) g_lph_bf[idx] = __float2bfloat16(lp_hw[idx]);
    }
}

// ---------------- edge_msg conversion: [E][172] fp32 -> bf16 [E][176] ----------------
__global__ void k_cvtmsg(const float* __restrict__ edge_msg)
{
    int j = blockIdx.x * 256 + threadIdx.x;   // uint2 units
    if (j >= EE * 44) return;
    int e = j / 44, c = j % 44;
    uint2 o = make_uint2(0u, 0u);
    if (c < 43)
        o = f4bf(*(const float4*)(edge_msg + (size_t)e * MSGD + c * 4));
    *(uint2*)(g_msgbf + (size_t)e * MSG_STRIDE + c * 4) = o;
}

// ---------------- zero atomic accumulators ----------------
__global__ void k_zero()
{
    int i = blockIdx.x * blockDim.x + threadIdx.x;
    float4 z = make_float4(0.f, 0.f, 0.f, 0.f);
    if (i < NN * 64) ((float4*)g_agg)[i] = z;
    if (i < NN / 2)  ((float4*)g_denom)[i] = z;
}

// ---------------- build GRU input (bf16), warp per node ----------------
__global__ __launch_bounds__(256) void k_build_aggr(
    const int* __restrict__ node_ids, const int* __restrict__ mem_last_update,
    const int* __restrict__ mem_rel_t, const int* __restrict__ mem_dst_id,
    const float* __restrict__ mem_table, const float* __restrict__ mem_msg_table,
    const float* __restrict__ mem_dir,
    const float* __restrict__ te_w, const float* __restrict__ te_b)
{
    const int lane = threadIdx.x & 31;
    const int nwarps = gridDim.x * 8;
    const float4 w4 = ((const float4*)te_w)[lane];
    const float4 b4 = ((const float4*)te_b)[lane];
    for (int n = blockIdx.x * 8 + (threadIdx.x >> 5); n < NN; n += nwarps) {
        const int nid = node_ids[n];
        const int did = mem_dst_id[nid];
        const float d0 = mem_dir[2 * nid], d1 = mem_dir[2 * nid + 1];
        const float4* sm4 = (const float4*)(mem_table + (size_t)nid * MEMD);
        const float4* dm4 = (const float4*)(mem_table + (size_t)did * MEMD);
        __nv_bfloat16* ag = g_aggrbf + (size_t)n * K_GI;
        __nv_bfloat16* hb = g_hbf + (size_t)n * MEMD;
        #pragma unroll
        for (int i = 0; i < 2; i++) {
            int j = lane + i * 32;
            float4 s = sm4[j], d = dm4[j];
            float4 c1 = make_float4(s.x*d0 + d.x*d1, s.y*d0 + d.y*d1,
                                    s.z*d0 + d.z*d1, s.w*d0 + d.w*d1);
            float4 c2 = make_float4(s.x*d1 + d.x*d0, s.y*d1 + d.y*d0,
                                    s.z*d1 + d.z*d0, s.w*d1 + d.w*d0);
            *(uint2*)(ag + 4 * j)       = f4bf(c1);
            *(uint2*)(ag + 256 + 4 * j) = f4bf(c2);
            *(uint2*)(hb + 4 * j)       = f4bf(s);
        }
        const float4* mg = (const float4*)(mem_msg_table + (size_t)nid * MSGD);
        for (int j = lane; j < MSGD / 4; j += 32)
            *(uint2*)(ag + 512 + 4 * j) = f4bf(mg[j]);
        float rt = (float)mem_rel_t[nid];
        float4 te = make_float4(__cosf(rt * w4.x + b4.x), __cosf(rt * w4.y + b4.y),
                                __cosf(rt * w4.z + b4.z), __cosf(rt * w4.w + b4.w));
        *(uint2*)(ag + 684 + 4 * lane) = f4bf(te);
        if (lane == 0) {
            *(uint2*)(ag + 812) = make_uint2(0u, 0u);   // zero pad
            g_lu[n] = (float)mem_last_update[nid];
        }
    }
}

// ---------------- GRU gate combine -> bf16 memory ----------------
__global__ void k_gru(const int* __restrict__ node_ids,
                      const float* __restrict__ mem_table)
{
    int i4 = blockIdx.x * blockDim.x + threadIdx.x;
    if (i4 >= NN * 64) return;
    int n = i4 >> 6, c4 = (i4 & 63) * 4;
    const float* gi = g_gi + (size_t)n * G3;
    const float* gh = g_gh + (size_t)n * G3;
    float4 ir = *(const float4*)(gi + c4);
    float4 iz = *(const float4*)(gi + 256 + c4);
    float4 in_ = *(const float4*)(gi + 512 + c4);
    float4 hr = *(const float4*)(gh + c4);
    float4 hz = *(const float4*)(gh + 256 + c4);
    float4 hn = *(const float4*)(gh + 512 + c4);
    float4 hv = *(const float4*)(mem_table + (size_t)node_ids[n] * MEMD + c4);
    float4 o;
    {
        float r = fsig(ir.x + hr.x), z = fsig(iz.x + hz.x);
        o.x = (1.f - z) * tanhf(in_.x + r * hn.x) + z * hv.x;
    }{
        float r = fsig(ir.y + hr.y), z = fsig(iz.y + hz.y);
        o.y = (1.f - z) * tanhf(in_.y + r * hn.y) + z * hv.y;
    }{
        float r = fsig(ir.z + hr.z), z = fsig(iz.z + hz.z);
        o.z = (1.f - z) * tanhf(in_.z + r * hn.z) + z * hv.z;
    }{
        float r = fsig(ir.w + hr.w), z = fsig(iz.w + hz.w);
        o.w = (1.f - z) * tanhf(in_.w + r * hn.w) + z * hv.w;
    }
    *(uint2*)(g_membf + (size_t)n * MEMD + c4) = f4bf(o);
}

// ---------------- z = skip(bf16) + agg/denom -> bf16 ----------------
__global__ void k_zfin()
{
    int i4 = blockIdx.x * blockDim.x + threadIdx.x;
    if (i4 >= NN * 64) return;
    int n = i4 >> 6, c4 = (i4 & 63) * 4;
    float rinv = 1.f / (g_denom[2 * n + (c4 >> 7)] + 1e-16f);
    float4 a = *(const float4*)(g_agg + (size_t)n * 256 + c4);
    uint2 sku = *(const uint2*)(g_qkvbf + (size_t)n * 1024 + 768 + c4);
    float2 s0 = bf2f(sku.x), s1 = bf2f(sku.y);
    float4 z = make_float4(s0.x + a.x * rinv, s0.y + a.y * rinv,
                           s1.x + a.z * rinv, s1.y + a.w * rinv);
    *(uint2*)(g_zbf + (size_t)n * MEMD + c4) = f4bf(z);
}

// ---------------- final dot + mask + sigmoid ----------------
__global__ __launch_bounds__(256) void k_final(
    const int* __restrict__ node_idx, const float* __restrict__ lp_fw,
    const float* __restrict__ lp_fb, float* __restrict__ out)
{
    const int r = blockIdx.x * 8 + (threadIdx.x >> 5);
    const int lane = threadIdx.x & 31;
    if (r >= 2 * BB) return;
    const float4* h4 = (const float4*)(g_hid + (size_t)r * 256);
    const float4* w4 = (const float4*)lp_fw;
    float4 a = h4[lane], b = w4[lane];
    float4 a2 = h4[32 + lane], b2 = w4[32 + lane];
    float s = a.x*b.x + a.y*b.y + a.z*b.z + a.w*b.w
            + a2.x*b2.x + a2.y*b2.y + a2.z*b2.z + a2.w*b2.w;
    #pragma unroll
    for (int o = 16; o; o >>= 1) s += __shfl_xor_sync(0xffffffffu, s, o);
    if (lane == 0) {
        int bidx = r & (BB - 1);
        float mask = (node_idx[bidx] < NN - 1) ? 1.f : 0.f;
        float val = (s + lp_fb[0]) * mask;
        out[r] = fsig(val);
    }
}

// ---------------- launch ----------------
extern "C" void kernel_launch(void* const* d_in, const int* in_sizes, int n_in,
                              void* d_out, int out_size)
{
    const int*   node_ids        = (const int*)  d_in[0];
    const int*   node_idx        = (const int*)  d_in[1];
    const int*   edge_idx        = (const int*)  d_in[2];
    const int*   mem_last_update = (const int*)  d_in[3];
    const int*   mem_rel_t       = (const int*)  d_in[4];
    const int*   mem_dst_id      = (const int*)  d_in[5];
    const float* edge_t          = (const float*)d_in[6];
    const float* edge_msg        = (const float*)d_in[7];
    const float* mem_table       = (const float*)d_in[8];
    const float* mem_msg_table   = (const float*)d_in[9];
    const float* mem_dir         = (const float*)d_in[10];
    const float* te_mem_w        = (const float*)d_in[11];
    const float* te_mem_b        = (const float*)d_in[12];
    const float* gru_w_ih        = (const float*)d_in[13];
    const float* gru_w_hh        = (const float*)d_in[14];
    const float* gru_b_ih        = (const float*)d_in[15];
    const float* gru_b_hh        = (const float*)d_in[16];
    const float* te_gnn_w        = (const float*)d_in[17];
    const float* te_gnn_b        = (const float*)d_in[18];
    const float* Wq              = (const float*)d_in[19];
    const float* bq              = (const float*)d_in[20];
    const float* Wk              = (const float*)d_in[21];
    const float* bk              = (const float*)d_in[22];
    const float* Wv              = (const float*)d_in[23];
    const float* bv              = (const float*)d_in[24];
    const float* We              = (const float*)d_in[25];
    const float* Wskip           = (const float*)d_in[26];
    const float* bskip           = (const float*)d_in[27];
    const float* lp_hw           = (const float*)d_in[28];
    const float* lp_hb           = (const float*)d_in[29];
    const float* lp_fw           = (const float*)d_in[30];
    const float* lp_fb           = (const float*)d_in[31];

    __nv_bfloat16 *p_aggrbf, *p_hbf, *p_membf, *p_zbf, *p_qkvbf,
                  *p_wih, *p_whh, *p_wq, *p_wk, *p_wv, *p_ws, *p_lph;
    float *p_gi, *p_gh, *p_hid;
    cudaGetSymbolAddress((void**)&p_aggrbf, g_aggrbf);
    cudaGetSymbolAddress((void**)&p_hbf,    g_hbf);
    cudaGetSymbolAddress((void**)&p_membf,  g_membf);
    cudaGetSymbolAddress((void**)&p_zbf,    g_zbf);
    cudaGetSymbolAddress((void**)&p_qkvbf,  g_qkvbf);
    cudaGetSymbolAddress((void**)&p_wih,    g_wih_bf);
    cudaGetSymbolAddress((void**)&p_whh,    g_whh_bf);
    cudaGetSymbolAddress((void**)&p_wq,     g_wq_bf);
    cudaGetSymbolAddress((void**)&p_wk,     g_wk_bf);
    cudaGetSymbolAddress((void**)&p_wv,     g_wv_bf);
    cudaGetSymbolAddress((void**)&p_ws,     g_ws_bf);
    cudaGetSymbolAddress((void**)&p_lph,    g_lph_bf);
    cudaGetSymbolAddress((void**)&p_gi,     g_gi);
    cudaGetSymbolAddress((void**)&p_gh,     g_gh);
    cudaGetSymbolAddress((void**)&p_hid,    g_hid);

    static bool s_init = false;
    static cudaStream_t s2;
    static cudaEvent_t evFork, evJoin;
    if (!s_init) {
        cudaStreamCreateWithFlags(&s2, cudaStreamNonBlocking);
        cudaEventCreateWithFlags(&evFork, cudaEventDisableTiming);
        cudaEventCreateWithFlags(&evJoin, cudaEventDisableTiming);
        cudaFuncSetAttribute(gemm5<0>, cudaFuncAttributeMaxDynamicSharedMemorySize, SMEM_BYTES);
        cudaFuncSetAttribute(gemm5<2>, cudaFuncAttributeMaxDynamicSharedMemorySize, SMEM_BYTES);
        cudaFuncSetAttribute(gemm5<3>, cudaFuncAttributeMaxDynamicSharedMemorySize, SMEM_BYTES);
        cudaFuncSetAttribute(gemm_attn, cudaFuncAttributeMaxDynamicSharedMemorySize, SMEM_BYTES);
        s_init = true;
    }

    // ---- fork: DRAM-bound prep (zero + msg cvt) overlaps the compute chain ----
    cudaEventRecord(evFork, 0);
    cudaStreamWaitEvent(s2, evFork, 0);
    k_zero<<<4096, 256, 0, s2>>>();
    k_cvtmsg<<<(EE * 44 + 255) / 256, 256, 0, s2>>>(edge_msg);
    cudaEventRecord(evJoin, s2);

    // ---- main: weight cvt + GRU chain + projections ----
    k_cvtw<<<dim3((768 * K_GI + 255) / 256, 8), 256>>>(
        gru_w_ih, gru_w_hh, Wq, Wk, Wv, Wskip, We, lp_hw);
    k_build_aggr<<<2048, 256>>>(node_ids, mem_last_update, mem_rel_t, mem_dst_id,
                                mem_table, mem_msg_table, mem_dir, te_mem_w, te_mem_b);
    gemm5<0><<<dim3(G3 / TBN, NN / TBM), 256, SMEM_BYTES>>>(
        p_aggrbf, K_GI, nullptr,
        p_wih, nullptr, nullptr, nullptr,
        gru_b_ih, nullptr, nullptr, nullptr,
        p_gi, G3, K_GI, 0, 0);
    gemm5<0><<<dim3(G3 / TBN, NN / TBM), 256, SMEM_BYTES>>>(
        p_hbf, 256, nullptr,
        p_whh, nullptr, nullptr, nullptr,
        gru_b_hh, nullptr, nullptr, nullptr,
        p_gh, G3, 256, 0, 0);
    k_gru<<<4096, 256>>>(node_ids, mem_table);

    // ---- fused q|k|v|skip projection (bf16 output) ----
    gemm5<3><<<dim3(1024 / TBN, NN / TBM), 256, SMEM_BYTES>>>(
        p_membf, 256, nullptr,
        p_wq, p_wk, p_wv, p_ws,
        bq, bk, bv, bskip,
        (float*)p_qkvbf, 1024, 256, 0, 1);

    // ---- join: zero + msg cvt must be done before attention ----
    cudaStreamWaitEvent(0, evJoin, 0);

    // ---- fused edge projection + time-enc + attention + scatter ----
    gemm_attn<<<dim3(2, EE / TBM), 256, SMEM_BYTES>>>(
        edge_idx, edge_t, te_gnn_w, te_gnn_b);

    k_zfin<<<4096, 256>>>();

    // ---- link predictor ----
    gemm5<2><<<dim3(256 / TBN, (2 * BB) / TBM), 256, SMEM_BYTES>>>(
        p_zbf, 256, node_idx,
        p_lph, nullptr, nullptr, nullptr,
        lp_hb, nullptr, nullptr, nullptr,
        p_hid, 256, 512, 1, 0);
    k_final<<<1024, 256>>>(node_idx, lp_fw, lp_fb, (float*)d_out);
}

// round 15
// speedup vs baseline: 1.0758x; 1.0156x over previous
#include <cuda_runtime.h>
#include <cuda_bf16.h>
#include <cuda_fp16.h>
#include <math.h>
#include <stdint.h>

// ---------------- problem constants ----------------
#define NN     16384
#define BB     4096
#define EE     131072
#define MEMD   256
#define TDD    128
#define MSGD   172
#define GRUIN  812
#define G3     768

// padded K dims (multiples of 16 halves -> no k-guards in pipeline)
#define K_GI   816     // 812 real + 4 zero
#define K_ATT  304     // 172 msg + 4 zero + 128 te  (19 k-tiles, no dead tile)
#define ATT_TE0 176
#define MSG_STRIDE 176

// ---------------- device scratch ----------------
__device__ __nv_bfloat16 g_aggrbf[(size_t)NN * K_GI];
__device__ __nv_bfloat16 g_hbf   [(size_t)NN * MEMD];
__device__ __nv_bfloat16 g_membf [(size_t)NN * MEMD];
__device__ __nv_bfloat16 g_zbf   [(size_t)NN * MEMD];
__device__ __nv_bfloat16 g_msgbf [(size_t)EE * MSG_STRIDE];
__device__ __nv_bfloat16 g_qkvbf [(size_t)NN * 1024];   // [q | k | v | skip] bf16
__device__ __nv_bfloat16 g_wih_bf[768 * K_GI];
__device__ __nv_bfloat16 g_whh_bf[768 * 256];
__device__ __nv_bfloat16 g_wq_bf [256 * 256];
__device__ __nv_bfloat16 g_wk_bf [256 * 256];
__device__ __nv_bfloat16 g_wv_bf [256 * 256];
__device__ __nv_bfloat16 g_ws_bf [256 * 256];
__device__ __nv_bfloat16 g_we_bf [256 * K_ATT];
__device__ __nv_bfloat16 g_lph_bf[256 * 512];

__device__ __half g_gih[(size_t)NN * G3];   // GRU gate pre-activations, fp16
__device__ __half g_ghh[(size_t)NN * G3];

__device__ float g_lu   [NN];
__device__ float g_denom[(size_t)NN * 2];
__device__ float g_agg  [(size_t)NN * MEMD];
__device__ float g_hid  [(size_t)2 * BB * 256];

// ---------------- tiles (champion parameters) ----------------
#define TBM 128
#define TBN 128
#define TBK 16
#define KPADH 24
#define WPR 12
#define STG 4
#define SMEM_BYTES (2 * STG * TBM * KPADH * 2)   // 49152

#define MMA_BF16(acc, af, bf)                                              \
    asm volatile(                                                          \
        "mma.sync.aligned.m16n8k16.row.col.f32.bf16.bf16.f32 "             \
        "{%0,%1,%2,%3}, {%4,%5,%6,%7}, {%8,%9}, {%0,%1,%2,%3};"            \
        : "+f"(acc[0]), "+f"(acc[1]), "+f"(acc[2]), "+f"(acc[3])           \
        : "r"(af[0]), "r"(af[1]), "r"(af[2]), "r"(af[3]),                  \
          "r"(bf[0]), "r"(bf[1]))

__device__ __forceinline__ void cp16(uint32_t dst, const void* src) {
    asm volatile("cp.async.cg.shared.global [%0], [%1], 16;"
                 :: "r"(dst), "l"(src));
}
#define CP_COMMIT asm volatile("cp.async.commit_group;")
#define CP_WAIT2  asm volatile("cp.async.wait_group 2;")

__device__ __forceinline__ unsigned pk(float a, float b) {
    unsigned x = (unsigned)__bfloat16_as_ushort(__float2bfloat16(a));
    unsigned y = (unsigned)__bfloat16_as_ushort(__float2bfloat16(b));
    return x | (y << 16);
}
__device__ __forceinline__ unsigned pkh(float a, float b) {   // fp16x2 pack
    __half2 h = __floats2half2_rn(a, b);
    return *reinterpret_cast<unsigned*>(&h);
}
__device__ __forceinline__ uint2 f4bf(float4 v) {
    return make_uint2(pk(v.x, v.y), pk(v.z, v.w));
}
__device__ __forceinline__ float2 bf2f(unsigned u) {
    __nv_bfloat162 h = *reinterpret_cast<__nv_bfloat162*>(&u);
    return __bfloat1622float2(h);
}
__device__ __forceinline__ float2 h2f(unsigned u) {
    __half2 h = *reinterpret_cast<__half2*>(&u);
    return __half22float2(h);
}
__device__ __forceinline__ float fsig(float x) {
    return 1.f / (1.f + __expf(-x));
}

// ================= bf16 cp.async tensor GEMM =================
// MODE 0: plain bf16 A. MODE 2: link-pred pair gather. MODE 3: 4 stacked W.
// out_fmt: 0 = fp32, 1 = bf16 pack, 2 = fp16 pack (C reinterpreted).
template<int MODE>
__global__ __launch_bounds__(256) void gemm5(
    const __nv_bfloat16* __restrict__ A, int strideA,
    const int* __restrict__ gidx,
    const __nv_bfloat16* __restrict__ W0c, const __nv_bfloat16* __restrict__ W1c,
    const __nv_bfloat16* __restrict__ W2c, const __nv_bfloat16* __restrict__ W3c,
    const float* __restrict__ b0c, const float* __restrict__ b1c,
    const float* __restrict__ b2c, const float* __restrict__ b3c,
    float* __restrict__ C, int Nout, int K, int do_relu, int out_fmt)
{
    extern __shared__ unsigned dynsmem[];
    unsigned* As32 = dynsmem;                      // [STG][128][WPR]
    unsigned* Ws32 = dynsmem + STG * TBM * WPR;
    const uint32_t sb_a = (uint32_t)__cvta_generic_to_shared(dynsmem);
    const uint32_t sb_w = sb_a + STG * TBM * KPADH * 2;

    const int t    = threadIdx.x;
    const int warp = t >> 5;
    const int lane = t & 31;
    const int g    = lane >> 2;
    const int tig  = lane & 3;
    const int wm   = warp >> 2;
    const int wn   = warp & 3;
    const int row0 = blockIdx.y * TBM;
    const int col0 = blockIdx.x * TBN;

    const __nv_bfloat16* Wsel = W0c;
    const float* bsel = b0c;
    int colL = col0;
    if (MODE == 3) {
        int grp = col0 >> 8;
        Wsel = (grp == 0) ? W0c : (grp == 1) ? W1c : (grp == 2) ? W2c : W3c;
        bsel = (grp == 0) ? b0c : (grp == 1) ? b1c : (grp == 2) ? b2c : b3c;
        colL = col0 & 255;
    }

    float acc[4][4][4];
    #pragma unroll
    for (int i = 0; i < 4; i++)
        #pragma unroll
        for (int j = 0; j < 4; j++)
            #pragma unroll
            for (int c = 0; c < 4; c++) acc[i][j][c] = 0.f;

    const int r  = t >> 1;
    const int ch = t & 1;

    auto issue = [&](int s, int k0) {
        int kb = k0 + ch * 8;
        const __nv_bfloat16* srcA;
        if (MODE == 2) {
            int gr = row0 + r;
            int b = gr & (BB - 1), side = gr >> 12;
            if (kb < 256) srcA = A + (size_t)gidx[b] * 256 + kb;
            else          srcA = A + (size_t)gidx[BB + side * BB + b] * 256 + (kb - 256);
        } else {
            srcA = A + (size_t)(row0 + r) * strideA + kb;
        }
        uint32_t off = (uint32_t)(((s * TBM + r) * KPADH + ch * 8) * 2);
        cp16(sb_a + off, srcA);
        cp16(sb_w + off, Wsel + (size_t)(colL + r) * K + kb);
    };
    auto compute = [&](int buf) {
        unsigned af[4][4], bf[4][2];
        #pragma unroll
        for (int mt = 0; mt < 4; mt++) {
            int rb = (buf * TBM) + wm * 64 + mt * 16;
            af[mt][0] = As32[(rb + g    ) * WPR + tig];
            af[mt][1] = As32[(rb + g + 8) * WPR + tig];
            af[mt][2] = As32[(rb + g    ) * WPR + tig + 4];
            af[mt][3] = As32[(rb + g + 8) * WPR + tig + 4];
        }
        #pragma unroll
        for (int nt = 0; nt < 4; nt++) {
            int nb = (buf * TBN) + wn * 32 + nt * 8;
            bf[nt][0] = Ws32[(nb + g) * WPR + tig];
            bf[nt][1] = Ws32[(nb + g) * WPR + tig + 4];
        }
        #pragma unroll
        for (int mt = 0; mt < 4; mt++)
            #pragma unroll
            for (int nt = 0; nt < 4; nt++)
                MMA_BF16(acc[mt][nt], af[mt], bf[nt]);
    };

    const int ktiles = K / TBK;
    issue(0, 0);       CP_COMMIT;
    issue(1, TBK);     CP_COMMIT;
    issue(2, 2 * TBK); CP_COMMIT;
    int fetch = 3;
    for (int j = 0; j < ktiles; j++) {
        CP_WAIT2;
        __syncthreads();
        compute(j % STG);
        if (fetch < ktiles) { issue(fetch % STG, fetch * TBK); fetch++; }
        CP_COMMIT;
    }

    __nv_bfloat16* Cb = reinterpret_cast<__nv_bfloat16*>(C);
    __half*        Ch = reinterpret_cast<__half*>(C);
    #pragma unroll
    for (int mt = 0; mt < 4; mt++) {
        int gr = row0 + wm * 64 + mt * 16 + g;
        #pragma unroll
        for (int nt = 0; nt < 4; nt++) {
            int nl = colL + wn * 32 + nt * 8 + tig * 2;
            int gc = col0 + wn * 32 + nt * 8 + tig * 2;
            float bb0 = bsel ? bsel[nl]     : 0.f;
            float bb1 = bsel ? bsel[nl + 1] : 0.f;
            float v0 = acc[mt][nt][0] + bb0;
            float v1 = acc[mt][nt][1] + bb1;
            float v2 = acc[mt][nt][2] + bb0;
            float v3 = acc[mt][nt][3] + bb1;
            if (do_relu) {
                v0 = fmaxf(v0, 0.f); v1 = fmaxf(v1, 0.f);
                v2 = fmaxf(v2, 0.f); v3 = fmaxf(v3, 0.f);
            }
            if (out_fmt == 1) {
                *reinterpret_cast<unsigned*>(Cb + (size_t)gr * Nout + gc)       = pk(v0, v1);
                *reinterpret_cast<unsigned*>(Cb + (size_t)(gr + 8) * Nout + gc) = pk(v2, v3);
            } else if (out_fmt == 2) {
                *reinterpret_cast<unsigned*>(Ch + (size_t)gr * Nout + gc)       = pkh(v0, v1);
                *reinterpret_cast<unsigned*>(Ch + (size_t)(gr + 8) * Nout + gc) = pkh(v2, v3);
            } else {
                *reinterpret_cast<float2*>(C + (size_t)gr * Nout + gc)       = make_float2(v0, v1);
                *reinterpret_cast<float2*>(C + (size_t)(gr + 8) * Nout + gc) = make_float2(v2, v3);
            }
        }
    }
}

// ========== fused edge GEMM (bf16) + time-enc + attention + scatter ==========
__global__ __launch_bounds__(256) void gemm_attn(
    const int* __restrict__ edge_idx, const float* __restrict__ edge_t,
    const float* __restrict__ te_w, const float* __restrict__ te_b)
{
    extern __shared__ unsigned dynsmem[];
    unsigned* As32 = dynsmem;
    unsigned* Ws32 = dynsmem + STG * TBM * WPR;
    const uint32_t sb_a = (uint32_t)__cvta_generic_to_shared(dynsmem);
    const uint32_t sb_w = sb_a + STG * TBM * KPADH * 2;

    __shared__ int   sSrc[128];
    __shared__ int   sDst[128];
    __shared__ float sPart[4][128];
    __shared__ float sX[128];

    const int t    = threadIdx.x;
    const int warp = t >> 5;
    const int lane = t & 31;
    const int g    = lane >> 2;
    const int tig  = lane & 3;
    const int wm   = warp >> 2;
    const int wn   = warp & 3;
    const int h    = blockIdx.x;
    const int row0 = blockIdx.y * TBM;
    const int col0 = h * 128;

    if (t < 128) {
        sSrc[t] = edge_idx[row0 + t];
        sDst[t] = edge_idx[EE + row0 + t];
    }

    float acc[4][4][4];
    #pragma unroll
    for (int i = 0; i < 4; i++)
        #pragma unroll
        for (int j = 0; j < 4; j++)
            #pragma unroll
            for (int c = 0; c < 4; c++) acc[i][j][c] = 0.f;

    const int r  = t >> 1;
    const int ch = t & 1;

    auto issue = [&](int s, int k0) {
        int kb = k0 + ch * 8;
        int gr = row0 + r;
        uint32_t off = (uint32_t)(((s * TBM + r) * KPADH + ch * 8) * 2);
        unsigned* ap = &As32[(s * TBM + r) * WPR + ch * 4];
        if (kb < MSG_STRIDE) {
            cp16(sb_a + off, g_msgbf + (size_t)gr * MSG_STRIDE + kb);
        } else {                         // te region: 176..304 (kb max 296)
            float rel = g_lu[edge_idx[gr]] - edge_t[gr];
            int c = kb - ATT_TE0;
            ap[0] = pk(__cosf(rel * te_w[c + 0] + te_b[c + 0]),
                       __cosf(rel * te_w[c + 1] + te_b[c + 1]));
            ap[1] = pk(__cosf(rel * te_w[c + 2] + te_b[c + 2]),
                       __cosf(rel * te_w[c + 3] + te_b[c + 3]));
            ap[2] = pk(__cosf(rel * te_w[c + 4] + te_b[c + 4]),
                       __cosf(rel * te_w[c + 5] + te_b[c + 5]));
            ap[3] = pk(__cosf(rel * te_w[c + 6] + te_b[c + 6]),
                       __cosf(rel * te_w[c + 7] + te_b[c + 7]));
        }
        cp16(sb_w + off, g_we_bf + (size_t)(col0 + r) * K_ATT + kb);
    };
    auto compute = [&](int buf) {
        unsigned af[4][4], bf[4][2];
        #pragma unroll
        for (int mt = 0; mt < 4; mt++) {
            int rb = (buf * TBM) + wm * 64 + mt * 16;
            af[mt][0] = As32[(rb + g    ) * WPR + tig];
            af[mt][1] = As32[(rb + g + 8) * WPR + tig];
            af[mt][2] = As32[(rb + g    ) * WPR + tig + 4];
            af[mt][3] = As32[(rb + g + 8) * WPR + tig + 4];
        }
        #pragma unroll
        for (int nt = 0; nt < 4; nt++) {
            int nb = (buf * TBN) + wn * 32 + nt * 8;
            bf[nt][0] = Ws32[(nb + g) * WPR + tig];
            bf[nt][1] = Ws32[(nb + g) * WPR + tig + 4];
        }
        #pragma unroll
        for (int mt = 0; mt < 4; mt++)
            #pragma unroll
            for (int nt = 0; nt < 4; nt++)
                MMA_BF16(acc[mt][nt], af[mt], bf[nt]);
    };

    const int ktiles = K_ATT / TBK;   // 19
    issue(0, 0);       CP_COMMIT;
    issue(1, TBK);     CP_COMMIT;
    issue(2, 2 * TBK); CP_COMMIT;
    int fetch = 3;
    for (int j = 0; j < ktiles; j++) {
        CP_WAIT2;
        __syncthreads();
        compute(j % STG);
        if (fetch < ktiles) { issue(fetch % STG, fetch * TBK); fetch++; }
        CP_COMMIT;
    }

    // ---- epilogue: logits q.(k+ep), bf16 gathers ----
    const int hoff = h * 128;
    float part[4][2];
    #pragma unroll
    for (int mt = 0; mt < 4; mt++) { part[mt][0] = 0.f; part[mt][1] = 0.f; }

    #pragma unroll
    for (int mt = 0; mt < 4; mt++) {
        int r1 = wm * 64 + mt * 16 + g;
        int r2 = r1 + 8;
        int d1 = sDst[r1], s1 = sSrc[r1];
        int d2 = sDst[r2], s2 = sSrc[r2];
        #pragma unroll
        for (int nt = 0; nt < 4; nt++) {
            int cl = hoff + wn * 32 + nt * 8 + tig * 2;
            float2 q1 = bf2f(*(const unsigned*)(g_qkvbf + (size_t)d1 * 1024 + cl));
            float2 k1 = bf2f(*(const unsigned*)(g_qkvbf + (size_t)s1 * 1024 + 256 + cl));
            float2 q2 = bf2f(*(const unsigned*)(g_qkvbf + (size_t)d2 * 1024 + cl));
            float2 k2 = bf2f(*(const unsigned*)(g_qkvbf + (size_t)s2 * 1024 + 256 + cl));
            part[mt][0] += q1.x * (k1.x + acc[mt][nt][0]) + q1.y * (k1.y + acc[mt][nt][1]);
            part[mt][1] += q2.x * (k2.x + acc[mt][nt][2]) + q2.y * (k2.y + acc[mt][nt][3]);
        }
    }
    #pragma unroll
    for (int mt = 0; mt < 4; mt++) {
        #pragma unroll
        for (int half = 0; half < 2; half++) {
            float p = part[mt][half];
            p += __shfl_xor_sync(0xffffffffu, p, 1);
            p += __shfl_xor_sync(0xffffffffu, p, 2);
            part[mt][half] = p;
        }
    }
    if (tig == 0) {
        #pragma unroll
        for (int mt = 0; mt < 4; mt++) {
            sPart[wn][wm * 64 + mt * 16 + g]     = part[mt][0];
            sPart[wn][wm * 64 + mt * 16 + g + 8] = part[mt][1];
        }
    }
    __syncthreads();

    if (t < 128) {
        const float scal = 0.08838834764831845f;   // 1/sqrt(128)
        float a = sPart[0][t] + sPart[1][t] + sPart[2][t] + sPart[3][t];
        float x = __expf(a * scal);
        sX[t] = x;
        atomicAdd(&g_denom[2 * sDst[t] + h], x);
    }
    __syncthreads();

    #pragma unroll
    for (int mt = 0; mt < 4; mt++) {
        int r1 = wm * 64 + mt * 16 + g;
        int r2 = r1 + 8;
        int d1 = sDst[r1], s1 = sSrc[r1];
        int d2 = sDst[r2], s2 = sSrc[r2];
        float x1 = sX[r1], x2 = sX[r2];
        #pragma unroll
        for (int nt = 0; nt < 4; nt++) {
            int cl = hoff + wn * 32 + nt * 8 + tig * 2;
            float2 v1 = bf2f(*(const unsigned*)(g_qkvbf + (size_t)s1 * 1024 + 512 + cl));
            float2 v2 = bf2f(*(const unsigned*)(g_qkvbf + (size_t)s2 * 1024 + 512 + cl));
            atomicAdd((float2*)(g_agg + (size_t)d1 * 256 + cl),
                      make_float2((v1.x + acc[mt][nt][0]) * x1,
                                  (v1.y + acc[mt][nt][1]) * x1));
            atomicAdd((float2*)(g_agg + (size_t)d2 * 256 + cl),
                      make_float2((v2.x + acc[mt][nt][2]) * x2,
                                  (v2.y + acc[mt][nt][3]) * x2));
        }
    }
}

// ---------------- weight conversion (once per launch) ----------------
__global__ void k_cvtw(
    const float* __restrict__ w_ih, const float* __restrict__ w_hh,
    const float* __restrict__ Wq, const float* __restrict__ Wk,
    const float* __restrict__ Wv, const float* __restrict__ Wskip,
    const float* __restrict__ We, const float* __restrict__ lp_hw)
{
    int seg = blockIdx.y;
    int idx = blockIdx.x * 256 + threadIdx.x;
    if (seg == 0) {                       // gru_w_ih: [768][812] -> [768][816]
        if (idx < 768 * K_GI) {
            int rr = idx / K_GI, c = idx % K_GI;
            g_wih_bf[idx] = __float2bfloat16(c < GRUIN ? w_ih[rr * GRUIN + c] : 0.f);
        }
    } else if (seg == 1) {
        if (idx < 768 * 256) g_whh_bf[idx] = __float2bfloat16(w_hh[idx]);
    } else if (seg == 2) {
        if (idx < 256 * 256) g_wq_bf[idx] = __float2bfloat16(Wq[idx]);
    } else if (seg == 3) {
        if (idx < 256 * 256) g_wk_bf[idx] = __float2bfloat16(Wk[idx]);
    } else if (seg == 4) {
        if (idx < 256 * 256) g_wv_bf[idx] = __float2bfloat16(Wv[idx]);
    } else if (seg == 5) {
        if (idx < 256 * 256) g_ws_bf[idx] = __float2bfloat16(Wskip[idx]);
    } else if (seg == 6) {                // We: [256][300] -> padded [256][304]
        if (idx < 256 * K_ATT) {
            int rr = idx / K_ATT, c = idx % K_ATT;
            float v = 0.f;
            if (c < MSGD)             v = We[rr * 300 + c];
            else if (c >= ATT_TE0)    v = We[rr * 300 + (c - 4)];
            g_we_bf[idx] = __float2bfloat16(v);
        }
    } else {
        if (idx < 256 * 512) g_lph_bf[idx] = __float2bfloat16(lp_hw[idx]);
    }
}

// ---------------- edge_msg conversion: [E][172] fp32 -> bf16 [E][176] ----------------
__global__ void k_cvtmsg(const float* __restrict__ edge_msg)
{
    int j = blockIdx.x * 256 + threadIdx.x;   // uint2 units
    if (j >= EE * 44) return;
    int e = j / 44, c = j % 44;
    uint2 o = make_uint2(0u, 0u);
    if (c < 43)
        o = f4bf(*(const float4*)(edge_msg + (size_t)e * MSGD + c * 4));
    *(uint2*)(g_msgbf + (size_t)e * MSG_STRIDE + c * 4) = o;
}

// ---------------- zero atomic accumulators ----------------
__global__ void k_zero()
{
    int i = blockIdx.x * blockDim.x + threadIdx.x;
    float4 z = make_float4(0.f, 0.f, 0.f, 0.f);
    if (i < NN * 64) ((float4*)g_agg)[i] = z;
    if (i < NN / 2)  ((float4*)g_denom)[i] = z;
}

// ---------------- build GRU input (bf16), warp per node ----------------
__global__ __launch_bounds__(256) void k_build_aggr(
    const int* __restrict__ node_ids, const int* __restrict__ mem_last_update,
    const int* __restrict__ mem_rel_t, const int* __restrict__ mem_dst_id,
    const float* __restrict__ mem_table, const float* __restrict__ mem_msg_table,
    const float* __restrict__ mem_dir,
    const float* __restrict__ te_w, const float* __restrict__ te_b)
{
    const int lane = threadIdx.x & 31;
    const int nwarps = gridDim.x * 8;
    const float4 w4 = ((const float4*)te_w)[lane];
    const float4 b4 = ((const float4*)te_b)[lane];
    for (int n = blockIdx.x * 8 + (threadIdx.x >> 5); n < NN; n += nwarps) {
        const int nid = node_ids[n];
        const int did = mem_dst_id[nid];
        const float d0 = mem_dir[2 * nid], d1 = mem_dir[2 * nid + 1];
        const float4* sm4 = (const float4*)(mem_table + (size_t)nid * MEMD);
        const float4* dm4 = (const float4*)(mem_table + (size_t)did * MEMD);
        __nv_bfloat16* ag = g_aggrbf + (size_t)n * K_GI;
        __nv_bfloat16* hb = g_hbf + (size_t)n * MEMD;
        #pragma unroll
        for (int i = 0; i < 2; i++) {
            int j = lane + i * 32;
            float4 s = sm4[j], d = dm4[j];
            float4 c1 = make_float4(s.x*d0 + d.x*d1, s.y*d0 + d.y*d1,
                                    s.z*d0 + d.z*d1, s.w*d0 + d.w*d1);
            float4 c2 = make_float4(s.x*d1 + d.x*d0, s.y*d1 + d.y*d0,
                                    s.z*d1 + d.z*d0, s.w*d1 + d.w*d0);
            *(uint2*)(ag + 4 * j)       = f4bf(c1);
            *(uint2*)(ag + 256 + 4 * j) = f4bf(c2);
            *(uint2*)(hb + 4 * j)       = f4bf(s);
        }
        const float4* mg = (const float4*)(mem_msg_table + (size_t)nid * MSGD);
        for (int j = lane; j < MSGD / 4; j += 32)
            *(uint2*)(ag + 512 + 4 * j) = f4bf(mg[j]);
        float rt = (float)mem_rel_t[nid];
        float4 te = make_float4(__cosf(rt * w4.x + b4.x), __cosf(rt * w4.y + b4.y),
                                __cosf(rt * w4.z + b4.z), __cosf(rt * w4.w + b4.w));
        *(uint2*)(ag + 684 + 4 * lane) = f4bf(te);
        if (lane == 0) {
            *(uint2*)(ag + 812) = make_uint2(0u, 0u);   // zero pad
            g_lu[n] = (float)mem_last_update[nid];
        }
    }
}

// ---------------- GRU gate combine (fp16 gates) -> bf16 memory ----------------
__global__ void k_gru(const int* __restrict__ node_ids,
                      const float* __restrict__ mem_table)
{
    int i4 = blockIdx.x * blockDim.x + threadIdx.x;
    if (i4 >= NN * 64) return;
    int n = i4 >> 6, c4 = (i4 & 63) * 4;
    const __half* gi = g_gih + (size_t)n * G3;
    const __half* gh = g_ghh + (size_t)n * G3;
    uint2 iru = *(const uint2*)(gi + c4);
    uint2 izu = *(const uint2*)(gi + 256 + c4);
    uint2 inu = *(const uint2*)(gi + 512 + c4);
    uint2 hru = *(const uint2*)(gh + c4);
    uint2 hzu = *(const uint2*)(gh + 256 + c4);
    uint2 hnu = *(const uint2*)(gh + 512 + c4);
    float2 ir0 = h2f(iru.x), ir1 = h2f(iru.y);
    float2 iz0 = h2f(izu.x), iz1 = h2f(izu.y);
    float2 in0 = h2f(inu.x), in1 = h2f(inu.y);
    float2 hr0 = h2f(hru.x), hr1 = h2f(hru.y);
    float2 hz0 = h2f(hzu.x), hz1 = h2f(hzu.y);
    float2 hn0 = h2f(hnu.x), hn1 = h2f(hnu.y);
    float4 hv = *(const float4*)(mem_table + (size_t)node_ids[n] * MEMD + c4);
    float4 o;
    {
        float r = fsig(ir0.x + hr0.x), z = fsig(iz0.x + hz0.x);
        o.x = (1.f - z) * tanhf(in0.x + r * hn0.x) + z * hv.x;
    }{
        float r = fsig(ir0.y + hr0.y), z = fsig(iz0.y + hz0.y);
        o.y = (1.f - z) * tanhf(in0.y + r * hn0.y) + z * hv.y;
    }{
        float r = fsig(ir1.x + hr1.x), z = fsig(iz1.x + hz1.x);
        o.z = (1.f - z) * tanhf(in1.x + r * hn1.x) + z * hv.z;
    }{
        float r = fsig(ir1.y + hr1.y), z = fsig(iz1.y + hz1.y);
        o.w = (1.f - z) * tanhf(in1.y + r * hn1.y) + z * hv.w;
    }
    *(uint2*)(g_membf + (size_t)n * MEMD + c4) = f4bf(o);
}

// ---------------- z = skip(bf16) + agg/denom -> bf16 ----------------
__global__ void k_zfin()
{
    int i4 = blockIdx.x * blockDim.x + threadIdx.x;
    if (i4 >= NN * 64) return;
    int n = i4 >> 6, c4 = (i4 & 63) * 4;
    float rinv = 1.f / (g_denom[2 * n + (c4 >> 7)] + 1e-16f);
    float4 a = *(const float4*)(g_agg + (size_t)n * 256 + c4);
    uint2 sku = *(const uint2*)(g_qkvbf + (size_t)n * 1024 + 768 + c4);
    float2 s0 = bf2f(sku.x), s1 = bf2f(sku.y);
    float4 z = make_float4(s0.x + a.x * rinv, s0.y + a.y * rinv,
                           s1.x + a.z * rinv, s1.y + a.w * rinv);
    *(uint2*)(g_zbf + (size_t)n * MEMD + c4) = f4bf(z);
}

// ---------------- final dot + mask + sigmoid ----------------
__global__ __launch_bounds__(256) void k_final(
    const int* __restrict__ node_idx, const float* __restrict__ lp_fw,
    const float* __restrict__ lp_fb, float* __restrict__ out)
{
    const int r = blockIdx.x * 8 + (threadIdx.x >> 5);
    const int lane = threadIdx.x & 31;
    if (r >= 2 * BB) return;
    const float4* h4 = (const float4*)(g_hid + (size_t)r * 256);
    const float4* w4 = (const float4*)lp_fw;
    float4 a = h4[lane], b = w4[lane];
    float4 a2 = h4[32 + lane], b2 = w4[32 + lane];
    float s = a.x*b.x + a.y*b.y + a.z*b.z + a.w*b.w
            + a2.x*b2.x + a2.y*b2.y + a2.z*b2.z + a2.w*b2.w;
    #pragma unroll
    for (int o = 16; o; o >>= 1) s += __shfl_xor_sync(0xffffffffu, s, o);
    if (lane == 0) {
        int bidx = r & (BB - 1);
        float mask = (node_idx[bidx] < NN - 1) ? 1.f : 0.f;
        float val = (s + lp_fb[0]) * mask;
        out[r] = fsig(val);
    }
}

// ---------------- launch ----------------
extern "C" void kernel_launch(void* const* d_in, const int* in_sizes, int n_in,
                              void* d_out, int out_size)
{
    const int*   node_ids        = (const int*)  d_in[0];
    const int*   node_idx        = (const int*)  d_in[1];
    const int*   edge_idx        = (const int*)  d_in[2];
    const int*   mem_last_update = (const int*)  d_in[3];
    const int*   mem_rel_t       = (const int*)  d_in[4];
    const int*   mem_dst_id      = (const int*)  d_in[5];
    const float* edge_t          = (const float*)d_in[6];
    const float* edge_msg        = (const float*)d_in[7];
    const float* mem_table       = (const float*)d_in[8];
    const float* mem_msg_table   = (const float*)d_in[9];
    const float* mem_dir         = (const float*)d_in[10];
    const float* te_mem_w        = (const float*)d_in[11];
    const float* te_mem_b        = (const float*)d_in[12];
    const float* gru_w_ih        = (const float*)d_in[13];
    const float* gru_w_hh        = (const float*)d_in[14];
    const float* gru_b_ih        = (const float*)d_in[15];
    const float* gru_b_hh        = (const float*)d_in[16];
    const float* te_gnn_w        = (const float*)d_in[17];
    const float* te_gnn_b        = (const float*)d_in[18];
    const float* Wq              = (const float*)d_in[19];
    const float* bq              = (const float*)d_in[20];
    const float* Wk              = (const float*)d_in[21];
    const float* bk              = (const float*)d_in[22];
    const float* Wv              = (const float*)d_in[23];
    const float* bv              = (const float*)d_in[24];
    const float* We              = (const float*)d_in[25];
    const float* Wskip           = (const float*)d_in[26];
    const float* bskip           = (const float*)d_in[27];
    const float* lp_hw           = (const float*)d_in[28];
    const float* lp_hb           = (const float*)d_in[29];
    const float* lp_fw           = (const float*)d_in[30];
    const float* lp_fb           = (const float*)d_in[31];

    __nv_bfloat16 *p_aggrbf, *p_hbf, *p_membf, *p_zbf, *p_qkvbf,
                  *p_wih, *p_whh, *p_wq, *p_wk, *p_wv, *p_ws, *p_lph;
    __half *p_gih, *p_ghh;
    float *p_hid;
    cudaGetSymbolAddress((void**)&p_aggrbf, g_aggrbf);
    cudaGetSymbolAddress((void**)&p_hbf,    g_hbf);
    cudaGetSymbolAddress((void**)&p_membf,  g_membf);
    cudaGetSymbolAddress((void**)&p_zbf,    g_zbf);
    cudaGetSymbolAddress((void**)&p_qkvbf,  g_qkvbf);
    cudaGetSymbolAddress((void**)&p_wih,    g_wih_bf);
    cudaGetSymbolAddress((void**)&p_whh,    g_whh_bf);
    cudaGetSymbolAddress((void**)&p_wq,     g_wq_bf);
    cudaGetSymbolAddress((void**)&p_wk,     g_wk_bf);
    cudaGetSymbolAddress((void**)&p_wv,     g_wv_bf);
    cudaGetSymbolAddress((void**)&p_ws,     g_ws_bf);
    cudaGetSymbolAddress((void**)&p_lph,    g_lph_bf);
    cudaGetSymbolAddress((void**)&p_gih,    g_gih);
    cudaGetSymbolAddress((void**)&p_ghh,    g_ghh);
    cudaGetSymbolAddress((void**)&p_hid,    g_hid);

    static bool s_init = false;
    static cudaStream_t s2;
    static cudaEvent_t evFork, evJoin;
    if (!s_init) {
        cudaStreamCreateWithFlags(&s2, cudaStreamNonBlocking);
        cudaEventCreateWithFlags(&evFork, cudaEventDisableTiming);
        cudaEventCreateWithFlags(&evJoin, cudaEventDisableTiming);
        cudaFuncSetAttribute(gemm5<0>, cudaFuncAttributeMaxDynamicSharedMemorySize, SMEM_BYTES);
        cudaFuncSetAttribute(gemm5<2>, cudaFuncAttributeMaxDynamicSharedMemorySize, SMEM_BYTES);
        cudaFuncSetAttribute(gemm5<3>, cudaFuncAttributeMaxDynamicSharedMemorySize, SMEM_BYTES);
        cudaFuncSetAttribute(gemm_attn, cudaFuncAttributeMaxDynamicSharedMemorySize, SMEM_BYTES);
        s_init = true;
    }

    // ---- fork: DRAM-bound prep overlaps the compute chain ----
    cudaEventRecord(evFork, 0);
    cudaStreamWaitEvent(s2, evFork, 0);
    k_zero<<<4096, 256, 0, s2>>>();
    k_cvtmsg<<<(EE * 44 + 255) / 256, 256, 0, s2>>>(edge_msg);
    cudaEventRecord(evJoin, s2);

    // ---- main: weight cvt + GRU chain + projections ----
    k_cvtw<<<dim3((768 * K_GI + 255) / 256, 8), 256>>>(
        gru_w_ih, gru_w_hh, Wq, Wk, Wv, Wskip, We, lp_hw);
    k_build_aggr<<<2048, 256>>>(node_ids, mem_last_update, mem_rel_t, mem_dst_id,
                                mem_table, mem_msg_table, mem_dir, te_mem_w, te_mem_b);
    gemm5<0><<<dim3(G3 / TBN, NN / TBM), 256, SMEM_BYTES>>>(
        p_aggrbf, K_GI, nullptr,
        p_wih, nullptr, nullptr, nullptr,
        gru_b_ih, nullptr, nullptr, nullptr,
        (float*)p_gih, G3, K_GI, 0, 2);
    gemm5<0><<<dim3(G3 / TBN, NN / TBM), 256, SMEM_BYTES>>>(
        p_hbf, 256, nullptr,
        p_whh, nullptr, nullptr, nullptr,
        gru_b_hh, nullptr, nullptr, nullptr,
        (float*)p_ghh, G3, 256, 0, 2);
    k_gru<<<4096, 256>>>(node_ids, mem_table);

    // ---- fused q|k|v|skip projection (bf16 output) ----
    gemm5<3><<<dim3(1024 / TBN, NN / TBM), 256, SMEM_BYTES>>>(
        p_membf, 256, nullptr,
        p_wq, p_wk, p_wv, p_ws,
        bq, bk, bv, bskip,
        (float*)p_qkvbf, 1024, 256, 0, 1);

    // ---- join: zero + msg cvt must be done before attention ----
    cudaStreamWaitEvent(0, evJoin, 0);

    // ---- fused edge projection + time-enc + attention + scatter ----
    gemm_attn<<<dim3(2, EE / TBM), 256, SMEM_BYTES>>>(
        edge_idx, edge_t, te_gnn_w, te_gnn_b);

    k_zfin<<<4096, 256>>>();

    // ---- link predictor ----
    gemm5<2><<<dim3(256 / TBN, (2 * BB) / TBM), 256, SMEM_BYTES>>>(
        p_zbf, 256, node_idx,
        p_lph, nullptr, nullptr, nullptr,
        lp_hb, nullptr, nullptr, nullptr,
        p_hid, 256, 512, 1, 0);
    k_final<<<1024, 256>>>(node_idx, lp_fw, lp_fb, (float*)d_out);
}

// round 16
// speedup vs baseline: 1.1231x; 1.0440x over previous
#include <cuda_runtime.h>
#include <cuda_bf16.h>
#include <cuda_fp16.h>
#include <math.h>
#include <stdint.h>

// ---------------- problem constants ----------------
#define NN     16384
#define BB     4096
#define EE     131072
#define MEMD   256
#define TDD    128
#define MSGD   172
#define GRUIN  812
#define G3     768

// padded K dims (multiples of 16 halves -> no k-guards in pipeline)
#define K_GI   816     // 812 real + 4 zero
#define K_ATT  304     // 172 msg + 4 zero + 128 te  (19 k-tiles)
#define ATT_TE0 176
#define MSG_STRIDE 176

// ---------------- device scratch ----------------
__device__ __nv_bfloat16 g_aggrbf[(size_t)NN * K_GI];
__device__ __nv_bfloat16 g_hbf   [(size_t)NN * MEMD];
__device__ __nv_bfloat16 g_membf [(size_t)NN * MEMD];
__device__ __nv_bfloat16 g_zbf   [(size_t)NN * MEMD];
__device__ __nv_bfloat16 g_msgbf [(size_t)EE * MSG_STRIDE];
__device__ __nv_bfloat16 g_qkvbf [(size_t)NN * 1024];   // [q | k | v | skip] bf16
__device__ __nv_bfloat16 g_hidbf [(size_t)2 * BB * 256];
__device__ __nv_bfloat16 g_wih_bf[768 * K_GI];
__device__ __nv_bfloat16 g_whh_bf[768 * 256];
__device__ __nv_bfloat16 g_wq_bf [256 * 256];
__device__ __nv_bfloat16 g_wk_bf [256 * 256];
__device__ __nv_bfloat16 g_wv_bf [256 * 256];
__device__ __nv_bfloat16 g_ws_bf [256 * 256];
__device__ __nv_bfloat16 g_we_bf [256 * K_ATT];
__device__ __nv_bfloat16 g_lph_bf[256 * 512];

__device__ __half g_gih[(size_t)NN * G3];   // GRU gate pre-activations, fp16
__device__ __half g_ghh[(size_t)NN * G3];

__device__ float g_lu   [NN];
__device__ float g_denom[(size_t)NN * 2];
__device__ float g_agg  [(size_t)NN * MEMD];

// ---------------- tiles (champion parameters) ----------------
#define TBM 128
#define TBN 128
#define TBK 16
#define KPADH 24
#define WPR 12
#define STG 4
#define SMEM_BYTES (2 * STG * TBM * KPADH * 2)   // 49152

#define MMA_BF16(acc, af, bf)                                              \
    asm volatile(                                                          \
        "mma.sync.aligned.m16n8k16.row.col.f32.bf16.bf16.f32 "             \
        "{%0,%1,%2,%3}, {%4,%5,%6,%7}, {%8,%9}, {%0,%1,%2,%3};"            \
        : "+f"(acc[0]), "+f"(acc[1]), "+f"(acc[2]), "+f"(acc[3])           \
        : "r"(af[0]), "r"(af[1]), "r"(af[2]), "r"(af[3]),                  \
          "r"(bf[0]), "r"(bf[1]))

__device__ __forceinline__ void cp16(uint32_t dst, const void* src) {
    asm volatile("cp.async.cg.shared.global [%0], [%1], 16;"
                 :: "r"(dst), "l"(src));
}
#define CP_COMMIT asm volatile("cp.async.commit_group;")
#define CP_WAIT2  asm volatile("cp.async.wait_group 2;")

__device__ __forceinline__ unsigned pk(float a, float b) {
    unsigned x = (unsigned)__bfloat16_as_ushort(__float2bfloat16(a));
    unsigned y = (unsigned)__bfloat16_as_ushort(__float2bfloat16(b));
    return x | (y << 16);
}
__device__ __forceinline__ unsigned pkh(float a, float b) {
    __half2 h = __floats2half2_rn(a, b);
    return *reinterpret_cast<unsigned*>(&h);
}
__device__ __forceinline__ uint2 f4bf(float4 v) {
    return make_uint2(pk(v.x, v.y), pk(v.z, v.w));
}
__device__ __forceinline__ float2 bf2f(unsigned u) {
    __nv_bfloat162 h = *reinterpret_cast<__nv_bfloat162*>(&u);
    return __bfloat1622float2(h);
}
__device__ __forceinline__ float2 h2f(unsigned u) {
    __half2 h = *reinterpret_cast<__half2*>(&u);
    return __half22float2(h);
}
__device__ __forceinline__ float fsig(float x) {
    return 1.f / (1.f + __expf(-x));
}

// ================= bf16 cp.async tensor GEMM =================
// MODE 0: plain bf16 A. MODE 2: link-pred pair gather. MODE 3: 4 stacked W.
// MODE 4: dual GRU GEMM — blockIdx.z=0: (A,W0c,b0c,K)->C ; z=1:
//   (W1c as A2 [stride 256], W2c, b1c, K=256) -> b3c (cast to half*).
// out_fmt: 0 = fp32, 1 = bf16 pack, 2 = fp16 pack (C reinterpreted).
template<int MODE>
__global__ __launch_bounds__(256) void gemm5(
    const __nv_bfloat16* __restrict__ A, int strideA,
    const int* __restrict__ gidx,
    const __nv_bfloat16* __restrict__ W0c, const __nv_bfloat16* __restrict__ W1c,
    const __nv_bfloat16* __restrict__ W2c, const __nv_bfloat16* __restrict__ W3c,
    const float* __restrict__ b0c, const float* __restrict__ b1c,
    const float* __restrict__ b2c, const float* __restrict__ b3c,
    float* __restrict__ C, int Nout, int K, int do_relu, int out_fmt)
{
    extern __shared__ unsigned dynsmem[];
    unsigned* As32 = dynsmem;                      // [STG][128][WPR]
    unsigned* Ws32 = dynsmem + STG * TBM * WPR;
    const uint32_t sb_a = (uint32_t)__cvta_generic_to_shared(dynsmem);
    const uint32_t sb_w = sb_a + STG * TBM * KPADH * 2;

    const int t    = threadIdx.x;
    const int warp = t >> 5;
    const int lane = t & 31;
    const int g    = lane >> 2;
    const int tig  = lane & 3;
    const int wm   = warp >> 2;
    const int wn   = warp & 3;
    const int row0 = blockIdx.y * TBM;
    const int col0 = blockIdx.x * TBN;

    const __nv_bfloat16* Asel = A;
    int sA   = strideA;
    int Ksel = K;
    const __nv_bfloat16* Wsel = W0c;
    const float* bsel = b0c;
    float* Cout = C;
    int colL = col0;
    if (MODE == 3) {
        int grp = col0 >> 8;
        Wsel = (grp == 0) ? W0c : (grp == 1) ? W1c : (grp == 2) ? W2c : W3c;
        bsel = (grp == 0) ? b0c : (grp == 1) ? b1c : (grp == 2) ? b2c : b3c;
        colL = col0 & 255;
    }
    if (MODE == 4 && blockIdx.z == 1) {
        Asel = W1c; sA = 256; Ksel = 256;
        Wsel = W2c; bsel = b1c;
        Cout = const_cast<float*>(b3c);
    }

    float acc[4][4][4];
    #pragma unroll
    for (int i = 0; i < 4; i++)
        #pragma unroll
        for (int j = 0; j < 4; j++)
            #pragma unroll
            for (int c = 0; c < 4; c++) acc[i][j][c] = 0.f;

    const int r  = t >> 1;
    const int ch = t & 1;

    auto issue = [&](int s, int k0) {
        int kb = k0 + ch * 8;
        const __nv_bfloat16* srcA;
        if (MODE == 2) {
            int gr = row0 + r;
            int b = gr & (BB - 1), side = gr >> 12;
            if (kb < 256) srcA = A + (size_t)gidx[b] * 256 + kb;
            else          srcA = A + (size_t)gidx[BB + side * BB + b] * 256 + (kb - 256);
        } else {
            srcA = Asel + (size_t)(row0 + r) * sA + kb;
        }
        uint32_t off = (uint32_t)(((s * TBM + r) * KPADH + ch * 8) * 2);
        cp16(sb_a + off, srcA);
        cp16(sb_w + off, Wsel + (size_t)(colL + r) * Ksel + kb);
    };
    auto compute = [&](int buf) {
        unsigned af[4][4], bf[4][2];
        #pragma unroll
        for (int mt = 0; mt < 4; mt++) {
            int rb = (buf * TBM) + wm * 64 + mt * 16;
            af[mt][0] = As32[(rb + g    ) * WPR + tig];
            af[mt][1] = As32[(rb + g + 8) * WPR + tig];
            af[mt][2] = As32[(rb + g    ) * WPR + tig + 4];
            af[mt][3] = As32[(rb + g + 8) * WPR + tig + 4];
        }
        #pragma unroll
        for (int nt = 0; nt < 4; nt++) {
            int nb = (buf * TBN) + wn * 32 + nt * 8;
            bf[nt][0] = Ws32[(nb + g) * WPR + tig];
            bf[nt][1] = Ws32[(nb + g) * WPR + tig + 4];
        }
        #pragma unroll
        for (int mt = 0; mt < 4; mt++)
            #pragma unroll
            for (int nt = 0; nt < 4; nt++)
                MMA_BF16(acc[mt][nt], af[mt], bf[nt]);
    };

    const int ktiles = Ksel / TBK;
    issue(0, 0);       CP_COMMIT;
    issue(1, TBK);     CP_COMMIT;
    issue(2, 2 * TBK); CP_COMMIT;
    int fetch = 3;
    for (int j = 0; j < ktiles; j++) {
        CP_WAIT2;
        __syncthreads();
        compute(j % STG);
        if (fetch < ktiles) { issue(fetch % STG, fetch * TBK); fetch++; }
        CP_COMMIT;
    }

    __nv_bfloat16* Cb = reinterpret_cast<__nv_bfloat16*>(Cout);
    __half*        Chh = reinterpret_cast<__half*>(Cout);
    #pragma unroll
    for (int mt = 0; mt < 4; mt++) {
        int gr = row0 + wm * 64 + mt * 16 + g;
        #pragma unroll
        for (int nt = 0; nt < 4; nt++) {
            int nl = colL + wn * 32 + nt * 8 + tig * 2;
            int gc = col0 + wn * 32 + nt * 8 + tig * 2;
            float bb0 = bsel ? bsel[nl]     : 0.f;
            float bb1 = bsel ? bsel[nl + 1] : 0.f;
            float v0 = acc[mt][nt][0] + bb0;
            float v1 = acc[mt][nt][1] + bb1;
            float v2 = acc[mt][nt][2] + bb0;
            float v3 = acc[mt][nt][3] + bb1;
            if (do_relu) {
                v0 = fmaxf(v0, 0.f); v1 = fmaxf(v1, 0.f);
                v2 = fmaxf(v2, 0.f); v3 = fmaxf(v3, 0.f);
            }
            if (out_fmt == 1) {
                *reinterpret_cast<unsigned*>(Cb + (size_t)gr * Nout + gc)       = pk(v0, v1);
                *reinterpret_cast<unsigned*>(Cb + (size_t)(gr + 8) * Nout + gc) = pk(v2, v3);
            } else if (out_fmt == 2) {
                *reinterpret_cast<unsigned*>(Chh + (size_t)gr * Nout + gc)       = pkh(v0, v1);
                *reinterpret_cast<unsigned*>(Chh + (size_t)(gr + 8) * Nout + gc) = pkh(v2, v3);
            } else {
                *reinterpret_cast<float2*>(Cout + (size_t)gr * Nout + gc)       = make_float2(v0, v1);
                *reinterpret_cast<float2*>(Cout + (size_t)(gr + 8) * Nout + gc) = make_float2(v2, v3);
            }
        }
    }
}

// ========== fused edge GEMM (bf16) + time-enc + attention + scatter ==========
__global__ __launch_bounds__(256) void gemm_attn(
    const int* __restrict__ edge_idx, const float* __restrict__ edge_t,
    const float* __restrict__ te_w, const float* __restrict__ te_b)
{
    extern __shared__ unsigned dynsmem[];
    unsigned* As32 = dynsmem;
    unsigned* Ws32 = dynsmem + STG * TBM * WPR;
    const uint32_t sb_a = (uint32_t)__cvta_generic_to_shared(dynsmem);
    const uint32_t sb_w = sb_a + STG * TBM * KPADH * 2;

    __shared__ int   sSrc[128];
    __shared__ int   sDst[128];
    __shared__ float sPart[4][128];
    __shared__ float sX[128];

    const int t    = threadIdx.x;
    const int warp = t >> 5;
    const int lane = t & 31;
    const int g    = lane >> 2;
    const int tig  = lane & 3;
    const int wm   = warp >> 2;
    const int wn   = warp & 3;
    const int h    = blockIdx.x;
    const int row0 = blockIdx.y * TBM;
    const int col0 = h * 128;

    if (t < 128) {
        sSrc[t] = edge_idx[row0 + t];
        sDst[t] = edge_idx[EE + row0 + t];
    }

    float acc[4][4][4];
    #pragma unroll
    for (int i = 0; i < 4; i++)
        #pragma unroll
        for (int j = 0; j < 4; j++)
            #pragma unroll
            for (int c = 0; c < 4; c++) acc[i][j][c] = 0.f;

    const int r  = t >> 1;
    const int ch = t & 1;

    auto issue = [&](int s, int k0) {
        int kb = k0 + ch * 8;
        int gr = row0 + r;
        uint32_t off = (uint32_t)(((s * TBM + r) * KPADH + ch * 8) * 2);
        unsigned* ap = &As32[(s * TBM + r) * WPR + ch * 4];
        if (kb < MSG_STRIDE) {
            cp16(sb_a + off, g_msgbf + (size_t)gr * MSG_STRIDE + kb);
        } else {                         // te region: 176..304
            float rel = g_lu[edge_idx[gr]] - edge_t[gr];
            int c = kb - ATT_TE0;
            ap[0] = pk(__cosf(rel * te_w[c + 0] + te_b[c + 0]),
                       __cosf(rel * te_w[c + 1] + te_b[c + 1]));
            ap[1] = pk(__cosf(rel * te_w[c + 2] + te_b[c + 2]),
                       __cosf(rel * te_w[c + 3] + te_b[c + 3]));
            ap[2] = pk(__cosf(rel * te_w[c + 4] + te_b[c + 4]),
                       __cosf(rel * te_w[c + 5] + te_b[c + 5]));
            ap[3] = pk(__cosf(rel * te_w[c + 6] + te_b[c + 6]),
                       __cosf(rel * te_w[c + 7] + te_b[c + 7]));
        }
        cp16(sb_w + off, g_we_bf + (size_t)(col0 + r) * K_ATT + kb);
    };
    auto compute = [&](int buf) {
        unsigned af[4][4], bf[4][2];
        #pragma unroll
        for (int mt = 0; mt < 4; mt++) {
            int rb = (buf * TBM) + wm * 64 + mt * 16;
            af[mt][0] = As32[(rb + g    ) * WPR + tig];
            af[mt][1] = As32[(rb + g + 8) * WPR + tig];
            af[mt][2] = As32[(rb + g    ) * WPR + tig + 4];
            af[mt][3] = As32[(rb + g + 8) * WPR + tig + 4];
        }
        #pragma unroll
        for (int nt = 0; nt < 4; nt++) {
            int nb = (buf * TBN) + wn * 32 + nt * 8;
            bf[nt][0] = Ws32[(nb + g) * WPR + tig];
            bf[nt][1] = Ws32[(nb + g) * WPR + tig + 4];
        }
        #pragma unroll
        for (int mt = 0; mt < 4; mt++)
            #pragma unroll
            for (int nt = 0; nt < 4; nt++)
                MMA_BF16(acc[mt][nt], af[mt], bf[nt]);
    };

    const int ktiles = K_ATT / TBK;   // 19
    issue(0, 0);       CP_COMMIT;
    issue(1, TBK);     CP_COMMIT;
    issue(2, 2 * TBK); CP_COMMIT;
    int fetch = 3;
    for (int j = 0; j < ktiles; j++) {
        CP_WAIT2;
        __syncthreads();
        compute(j % STG);
        if (fetch < ktiles) { issue(fetch % STG, fetch * TBK); fetch++; }
        CP_COMMIT;
    }

    // ---- epilogue: logits q.(k+ep), bf16 gathers ----
    const int hoff = h * 128;
    float part[4][2];
    #pragma unroll
    for (int mt = 0; mt < 4; mt++) { part[mt][0] = 0.f; part[mt][1] = 0.f; }

    #pragma unroll
    for (int mt = 0; mt < 4; mt++) {
        int r1 = wm * 64 + mt * 16 + g;
        int r2 = r1 + 8;
        int d1 = sDst[r1], s1 = sSrc[r1];
        int d2 = sDst[r2], s2 = sSrc[r2];
        #pragma unroll
        for (int nt = 0; nt < 4; nt++) {
            int cl = hoff + wn * 32 + nt * 8 + tig * 2;
            float2 q1 = bf2f(*(const unsigned*)(g_qkvbf + (size_t)d1 * 1024 + cl));
            float2 k1 = bf2f(*(const unsigned*)(g_qkvbf + (size_t)s1 * 1024 + 256 + cl));
            float2 q2 = bf2f(*(const unsigned*)(g_qkvbf + (size_t)d2 * 1024 + cl));
            float2 k2 = bf2f(*(const unsigned*)(g_qkvbf + (size_t)s2 * 1024 + 256 + cl));
            part[mt][0] += q1.x * (k1.x + acc[mt][nt][0]) + q1.y * (k1.y + acc[mt][nt][1]);
            part[mt][1] += q2.x * (k2.x + acc[mt][nt][2]) + q2.y * (k2.y + acc[mt][nt][3]);
        }
    }
    #pragma unroll
    for (int mt = 0; mt < 4; mt++) {
        #pragma unroll
        for (int half = 0; half < 2; half++) {
            float p = part[mt][half];
            p += __shfl_xor_sync(0xffffffffu, p, 1);
            p += __shfl_xor_sync(0xffffffffu, p, 2);
            part[mt][half] = p;
        }
    }
    if (tig == 0) {
        #pragma unroll
        for (int mt = 0; mt < 4; mt++) {
            sPart[wn][wm * 64 + mt * 16 + g]     = part[mt][0];
            sPart[wn][wm * 64 + mt * 16 + g + 8] = part[mt][1];
        }
    }
    __syncthreads();

    if (t < 128) {
        const float scal = 0.08838834764831845f;   // 1/sqrt(128)
        float a = sPart[0][t] + sPart[1][t] + sPart[2][t] + sPart[3][t];
        float x = __expf(a * scal);
        sX[t] = x;
        atomicAdd(&g_denom[2 * sDst[t] + h], x);
    }
    __syncthreads();

    #pragma unroll
    for (int mt = 0; mt < 4; mt++) {
        int r1 = wm * 64 + mt * 16 + g;
        int r2 = r1 + 8;
        int d1 = sDst[r1], s1 = sSrc[r1];
        int d2 = sDst[r2], s2 = sSrc[r2];
        float x1 = sX[r1], x2 = sX[r2];
        #pragma unroll
        for (int nt = 0; nt < 4; nt++) {
            int cl = hoff + wn * 32 + nt * 8 + tig * 2;
            float2 v1 = bf2f(*(const unsigned*)(g_qkvbf + (size_t)s1 * 1024 + 512 + cl));
            float2 v2 = bf2f(*(const unsigned*)(g_qkvbf + (size_t)s2 * 1024 + 512 + cl));
            atomicAdd((float2*)(g_agg + (size_t)d1 * 256 + cl),
                      make_float2((v1.x + acc[mt][nt][0]) * x1,
                                  (v1.y + acc[mt][nt][1]) * x1));
            atomicAdd((float2*)(g_agg + (size_t)d2 * 256 + cl),
                      make_float2((v2.x + acc[mt][nt][2]) * x2,
                                  (v2.y + acc[mt][nt][3]) * x2));
        }
    }
}

// ---------------- weight conversion (once per launch) ----------------
__global__ void k_cvtw(
    const float* __restrict__ w_ih, const float* __restrict__ w_hh,
    const float* __restrict__ Wq, const float* __restrict__ Wk,
    const float* __restrict__ Wv, const float* __restrict__ Wskip,
    const float* __restrict__ We, const float* __restrict__ lp_hw)
{
    int seg = blockIdx.y;
    int idx = blockIdx.x * 256 + threadIdx.x;
    if (seg == 0) {                       // gru_w_ih: [768][812] -> [768][816]
        if (idx < 768 * K_GI) {
            int rr = idx / K_GI, c = idx % K_GI;
            g_wih_bf[idx] = __float2bfloat16(c < GRUIN ? w_ih[rr * GRUIN + c] : 0.f);
        }
    } else if (seg == 1) {
        if (idx < 768 * 256) g_whh_bf[idx] = __float2bfloat16(w_hh[idx]);
    } else if (seg == 2) {
        if (idx < 256 * 256) g_wq_bf[idx] = __float2bfloat16(Wq[idx]);
    } else if (seg == 3) {
        if (idx < 256 * 256) g_wk_bf[idx] = __float2bfloat16(Wk[idx]);
    } else if (seg == 4) {
        if (idx < 256 * 256) g_wv_bf[idx] = __float2bfloat16(Wv[idx]);
    } else if (seg == 5) {
        if (idx < 256 * 256) g_ws_bf[idx] = __float2bfloat16(Wskip[idx]);
    } else if (seg == 6) {                // We: [256][300] -> padded [256][304]
        if (idx < 256 * K_ATT) {
            int rr = idx / K_ATT, c = idx % K_ATT;
            float v = 0.f;
            if (c < MSGD)             v = We[rr * 300 + c];
            else if (c >= ATT_TE0)    v = We[rr * 300 + (c - 4)];
            g_we_bf[idx] = __float2bfloat16(v);
        }
    } else {
        if (idx < 256 * 512) g_lph_bf[idx] = __float2bfloat16(lp_hw[idx]);
    }
}

// ---------------- edge_msg conversion: [E][172] fp32 -> bf16 [E][176] ----------------
__global__ void k_cvtmsg(const float* __restrict__ edge_msg)
{
    int j = blockIdx.x * 256 + threadIdx.x;   // uint2 units
    if (j >= EE * 44) return;
    int e = j / 44, c = j % 44;
    uint2 o = make_uint2(0u, 0u);
    if (c < 43)
        o = f4bf(*(const float4*)(edge_msg + (size_t)e * MSGD + c * 4));
    *(uint2*)(g_msgbf + (size_t)e * MSG_STRIDE + c * 4) = o;
}

// ---------------- zero atomic accumulators ----------------
__global__ void k_zero()
{
    int i = blockIdx.x * blockDim.x + threadIdx.x;
    float4 z = make_float4(0.f, 0.f, 0.f, 0.f);
    if (i < NN * 64) ((float4*)g_agg)[i] = z;
    if (i < NN / 2)  ((float4*)g_denom)[i] = z;
}

// ---------------- build GRU input (bf16), warp per node ----------------
__global__ __launch_bounds__(256) void k_build_aggr(
    const int* __restrict__ node_ids, const int* __restrict__ mem_last_update,
    const int* __restrict__ mem_rel_t, const int* __restrict__ mem_dst_id,
    const float* __restrict__ mem_table, const float* __restrict__ mem_msg_table,
    const float* __restrict__ mem_dir,
    const float* __restrict__ te_w, const float* __restrict__ te_b)
{
    const int lane = threadIdx.x & 31;
    const int nwarps = gridDim.x * 8;
    const float4 w4 = ((const float4*)te_w)[lane];
    const float4 b4 = ((const float4*)te_b)[lane];
    for (int n = blockIdx.x * 8 + (threadIdx.x >> 5); n < NN; n += nwarps) {
        const int nid = node_ids[n];
        const int did = mem_dst_id[nid];
        const float d0 = mem_dir[2 * nid], d1 = mem_dir[2 * nid + 1];
        const float4* sm4 = (const float4*)(mem_table + (size_t)nid * MEMD);
        const float4* dm4 = (const float4*)(mem_table + (size_t)did * MEMD);
        __nv_bfloat16* ag = g_aggrbf + (size_t)n * K_GI;
        __nv_bfloat16* hb = g_hbf + (size_t)n * MEMD;
        #pragma unroll
        for (int i = 0; i < 2; i++) {
            int j = lane + i * 32;
            float4 s = sm4[j], d = dm4[j];
            float4 c1 = make_float4(s.x*d0 + d.x*d1, s.y*d0 + d.y*d1,
                                    s.z*d0 + d.z*d1, s.w*d0 + d.w*d1);
            float4 c2 = make_float4(s.x*d1 + d.x*d0, s.y*d1 + d.y*d0,
                                    s.z*d1 + d.z*d0, s.w*d1 + d.w*d0);
            *(uint2*)(ag + 4 * j)       = f4bf(c1);
            *(uint2*)(ag + 256 + 4 * j) = f4bf(c2);
            *(uint2*)(hb + 4 * j)       = f4bf(s);
        }
        const float4* mg = (const float4*)(mem_msg_table + (size_t)nid * MSGD);
        for (int j = lane; j < MSGD / 4; j += 32)
            *(uint2*)(ag + 512 + 4 * j) = f4bf(mg[j]);
        float rt = (float)mem_rel_t[nid];
        float4 te = make_float4(__cosf(rt * w4.x + b4.x), __cosf(rt * w4.y + b4.y),
                                __cosf(rt * w4.z + b4.z), __cosf(rt * w4.w + b4.w));
        *(uint2*)(ag + 684 + 4 * lane) = f4bf(te);
        if (lane == 0) {
            *(uint2*)(ag + 812) = make_uint2(0u, 0u);   // zero pad
            g_lu[n] = (float)mem_last_update[nid];
        }
    }
}

// ---------------- GRU gate combine (fp16 gates) -> bf16 memory ----------------
__global__ void k_gru(const int* __restrict__ node_ids,
                      const float* __restrict__ mem_table)
{
    int i4 = blockIdx.x * blockDim.x + threadIdx.x;
    if (i4 >= NN * 64) return;
    int n = i4 >> 6, c4 = (i4 & 63) * 4;
    const __half* gi = g_gih + (size_t)n * G3;
    const __half* gh = g_ghh + (size_t)n * G3;
    uint2 iru = *(const uint2*)(gi + c4);
    uint2 izu = *(const uint2*)(gi + 256 + c4);
    uint2 inu = *(const uint2*)(gi + 512 + c4);
    uint2 hru = *(const uint2*)(gh + c4);
    uint2 hzu = *(const uint2*)(gh + 256 + c4);
    uint2 hnu = *(const uint2*)(gh + 512 + c4);
    float2 ir0 = h2f(iru.x), ir1 = h2f(iru.y);
    float2 iz0 = h2f(izu.x), iz1 = h2f(izu.y);
    float2 in0 = h2f(inu.x), in1 = h2f(inu.y);
    float2 hr0 = h2f(hru.x), hr1 = h2f(hru.y);
    float2 hz0 = h2f(hzu.x), hz1 = h2f(hzu.y);
    float2 hn0 = h2f(hnu.x), hn1 = h2f(hnu.y);
    float4 hv = *(const float4*)(mem_table + (size_t)node_ids[n] * MEMD + c4);
    float4 o;
    {
        float r = fsig(ir0.x + hr0.x), z = fsig(iz0.x + hz0.x);
        o.x = (1.f - z) * tanhf(in0.x + r * hn0.x) + z * hv.x;
    }{
        float r = fsig(ir0.y + hr0.y), z = fsig(iz0.y + hz0.y);
        o.y = (1.f - z) * tanhf(in0.y + r * hn0.y) + z * hv.y;
    }{
        float r = fsig(ir1.x + hr1.x), z = fsig(iz1.x + hz1.x);
        o.z = (1.f - z) * tanhf(in1.x + r * hn1.x) + z * hv.z;
    }{
        float r = fsig(ir1.y + hr1.y), z = fsig(iz1.y + hz1.y);
        o.w = (1.f - z) * tanhf(in1.y + r * hn1.y) + z * hv.w;
    }
    *(uint2*)(g_membf + (size_t)n * MEMD + c4) = f4bf(o);
}

// ---------------- z = skip(bf16) + agg/denom -> bf16 ----------------
__global__ void k_zfin()
{
    int i4 = blockIdx.x * blockDim.x + threadIdx.x;
    if (i4 >= NN * 64) return;
    int n = i4 >> 6, c4 = (i4 & 63) * 4;
    float rinv = 1.f / (g_denom[2 * n + (c4 >> 7)] + 1e-16f);
    float4 a = *(const float4*)(g_agg + (size_t)n * 256 + c4);
    uint2 sku = *(const uint2*)(g_qkvbf + (size_t)n * 1024 + 768 + c4);
    float2 s0 = bf2f(sku.x), s1 = bf2f(sku.y);
    float4 z = make_float4(s0.x + a.x * rinv, s0.y + a.y * rinv,
                           s1.x + a.z * rinv, s1.y + a.w * rinv);
    *(uint2*)(g_zbf + (size_t)n * MEMD + c4) = f4bf(z);
}

// ---------------- final dot (bf16 hid) + mask + sigmoid ----------------
__global__ __launch_bounds__(256) void k_final(
    const int* __restrict__ node_idx, const float* __restrict__ lp_fw,
    const float* __restrict__ lp_fb, float* __restrict__ out)
{
    const int r = blockIdx.x * 8 + (threadIdx.x >> 5);
    const int lane = threadIdx.x & 31;
    if (r >= 2 * BB) return;
    uint4 hv = ((const uint4*)(g_hidbf + (size_t)r * 256))[lane];   // 8 bf16
    float2 a0 = bf2f(hv.x), a1 = bf2f(hv.y), a2 = bf2f(hv.z), a3 = bf2f(hv.w);
    float4 w0 = ((const float4*)lp_fw)[2 * lane];
    float4 w1 = ((const float4*)lp_fw)[2 * lane + 1];
    float s = a0.x*w0.x + a0.y*w0.y + a1.x*w0.z + a1.y*w0.w
            + a2.x*w1.x + a2.y*w1.y + a3.x*w1.z + a3.y*w1.w;
    #pragma unroll
    for (int o = 16; o; o >>= 1) s += __shfl_xor_sync(0xffffffffu, s, o);
    if (lane == 0) {
        int bidx = r & (BB - 1);
        float mask = (node_idx[bidx] < NN - 1) ? 1.f : 0.f;
        float val = (s + lp_fb[0]) * mask;
        out[r] = fsig(val);
    }
}

// ---------------- launch ----------------
extern "C" void kernel_launch(void* const* d_in, const int* in_sizes, int n_in,
                              void* d_out, int out_size)
{
    const int*   node_ids        = (const int*)  d_in[0];
    const int*   node_idx        = (const int*)  d_in[1];
    const int*   edge_idx        = (const int*)  d_in[2];
    const int*   mem_last_update = (const int*)  d_in[3];
    const int*   mem_rel_t       = (const int*)  d_in[4];
    const int*   mem_dst_id      = (const int*)  d_in[5];
    const float* edge_t          = (const float*)d_in[6];
    const float* edge_msg        = (const float*)d_in[7];
    const float* mem_table       = (const float*)d_in[8];
    const float* mem_msg_table   = (const float*)d_in[9];
    const float* mem_dir         = (const float*)d_in[10];
    const float* te_mem_w        = (const float*)d_in[11];
    const float* te_mem_b        = (const float*)d_in[12];
    const float* gru_w_ih        = (const float*)d_in[13];
    const float* gru_w_hh        = (const float*)d_in[14];
    const float* gru_b_ih        = (const float*)d_in[15];
    const float* gru_b_hh        = (const float*)d_in[16];
    const float* te_gnn_w        = (const float*)d_in[17];
    const float* te_gnn_b        = (const float*)d_in[18];
    const float* Wq              = (const float*)d_in[19];
    const float* bq              = (const float*)d_in[20];
    const float* Wk              = (const float*)d_in[21];
    const float* bk              = (const float*)d_in[22];
    const float* Wv              = (const float*)d_in[23];
    const float* bv              = (const float*)d_in[24];
    const float* We              = (const float*)d_in[25];
    const float* Wskip           = (const float*)d_in[26];
    const float* bskip           = (const float*)d_in[27];
    const float* lp_hw           = (const float*)d_in[28];
    const float* lp_hb           = (const float*)d_in[29];
    const float* lp_fw           = (const float*)d_in[30];
    const float* lp_fb           = (const float*)d_in[31];

    __nv_bfloat16 *p_aggrbf, *p_hbf, *p_membf, *p_zbf, *p_qkvbf, *p_hidbf,
                  *p_wih, *p_whh, *p_wq, *p_wk, *p_wv, *p_ws, *p_lph;
    __half *p_gih, *p_ghh;
    cudaGetSymbolAddress((void**)&p_aggrbf, g_aggrbf);
    cudaGetSymbolAddress((void**)&p_hbf,    g_hbf);
    cudaGetSymbolAddress((void**)&p_membf,  g_membf);
    cudaGetSymbolAddress((void**)&p_zbf,    g_zbf);
    cudaGetSymbolAddress((void**)&p_qkvbf,  g_qkvbf);
    cudaGetSymbolAddress((void**)&p_hidbf,  g_hidbf);
    cudaGetSymbolAddress((void**)&p_wih,    g_wih_bf);
    cudaGetSymbolAddress((void**)&p_whh,    g_whh_bf);
    cudaGetSymbolAddress((void**)&p_wq,     g_wq_bf);
    cudaGetSymbolAddress((void**)&p_wk,     g_wk_bf);
    cudaGetSymbolAddress((void**)&p_wv,     g_wv_bf);
    cudaGetSymbolAddress((void**)&p_ws,     g_ws_bf);
    cudaGetSymbolAddress((void**)&p_lph,    g_lph_bf);
    cudaGetSymbolAddress((void**)&p_gih,    g_gih);
    cudaGetSymbolAddress((void**)&p_ghh,    g_ghh);

    static bool s_init = false;
    static cudaStream_t s2;
    static cudaEvent_t evFork, evJoin;
    if (!s_init) {
        cudaStreamCreateWithFlags(&s2, cudaStreamNonBlocking);
        cudaEventCreateWithFlags(&evFork, cudaEventDisableTiming);
        cudaEventCreateWithFlags(&evJoin, cudaEventDisableTiming);
        cudaFuncSetAttribute(gemm5<2>, cudaFuncAttributeMaxDynamicSharedMemorySize, SMEM_BYTES);
        cudaFuncSetAttribute(gemm5<3>, cudaFuncAttributeMaxDynamicSharedMemorySize, SMEM_BYTES);
        cudaFuncSetAttribute(gemm5<4>, cudaFuncAttributeMaxDynamicSharedMemorySize, SMEM_BYTES);
        cudaFuncSetAttribute(gemm_attn, cudaFuncAttributeMaxDynamicSharedMemorySize, SMEM_BYTES);
        s_init = true;
    }

    // ---- fork: DRAM-bound prep overlaps the compute chain ----
    cudaEventRecord(evFork, 0);
    cudaStreamWaitEvent(s2, evFork, 0);
    k_zero<<<4096, 256, 0, s2>>>();
    k_cvtmsg<<<(EE * 44 + 255) / 256, 256, 0, s2>>>(edge_msg);
    cudaEventRecord(evJoin, s2);

    // ---- main: weight cvt + GRU chain + projections ----
    k_cvtw<<<dim3((768 * K_GI + 255) / 256, 8), 256>>>(
        gru_w_ih, gru_w_hh, Wq, Wk, Wv, Wskip, We, lp_hw);
    k_build_aggr<<<2048, 256>>>(node_ids, mem_last_update, mem_rel_t, mem_dst_id,
                                mem_table, mem_msg_table, mem_dir, te_mem_w, te_mem_b);
    // merged gi (z=0) + gh (z=1) GEMMs
    gemm5<4><<<dim3(G3 / TBN, NN / TBM, 2), 256, SMEM_BYTES>>>(
        p_aggrbf, K_GI, nullptr,
        p_wih, p_hbf, p_whh, nullptr,
        gru_b_ih, gru_b_hh, nullptr, (const float*)p_ghh,
        (float*)p_gih, G3, K_GI, 0, 2);
    k_gru<<<4096, 256>>>(node_ids, mem_table);

    // ---- fused q|k|v|skip projection (bf16 output) ----
    gemm5<3><<<dim3(1024 / TBN, NN / TBM), 256, SMEM_BYTES>>>(
        p_membf, 256, nullptr,
        p_wq, p_wk, p_wv, p_ws,
        bq, bk, bv, bskip,
        (float*)p_qkvbf, 1024, 256, 0, 1);

    // ---- join: zero + msg cvt must be done before attention ----
    cudaStreamWaitEvent(0, evJoin, 0);

    // ---- fused edge projection + time-enc + attention + scatter ----
    gemm_attn<<<dim3(2, EE / TBM), 256, SMEM_BYTES>>>(
        edge_idx, edge_t, te_gnn_w, te_gnn_b);

    k_zfin<<<4096, 256>>>();

    // ---- link predictor (bf16 hidden) ----
    gemm5<2><<<dim3(256 / TBN, (2 * BB) / TBM), 256, SMEM_BYTES>>>(
        p_zbf, 256, node_idx,
        p_lph, nullptr, nullptr, nullptr,
        lp_hb, nullptr, nullptr, nullptr,
        (float*)p_hidbf, 256, 512, 1, 1);
    k_final<<<1024, 256>>>(node_idx, lp_fw, lp_fb, (float*)d_out);
}